// round 5
// baseline (speedup 1.0000x reference)
#include <cuda_runtime.h>
#include <cuda_bf16.h>
#include <cstdint>
#include <cstddef>

#define DEV_INLINE __device__ __forceinline__

namespace {
constexpr int kB    = 64;
constexpr int kT    = 512;
constexpr int kDin  = 512;
constexpr int kDh   = 1024;
constexpr int kDout = 1024;
constexpr int kNC   = 64;      // persistent CTA count (<= #SMs, 1 CTA/SM -> co-resident)
constexpr int kKP   = kDh / 2; // 512 k-pairs
}

// ---------------- device scratch (no allocs allowed) ------------------------
__device__ float g_xbuf[(size_t)kT * 3 * kB * kDh];        // [t][gate][b][j], x-proj + bias
__device__ float g_hs[(size_t)(kT + 1) * kB * kDh];        // [t][b][j]
__device__ float g_z[(size_t)kB * kDh];                    // z gate (per step)
__device__ uint2 g_hpk[(size_t)kB * kKP];                  // h packed: {bf16x2 hi, bf16x2 lo} per k-pair
__device__ uint2 g_rhpk[(size_t)kB * kKP];                 // r*h packed
__device__ uint2 g_wpk[(size_t)3 * kDh * kKP];             // W*_h packed, [gate][j][kpair]
__device__ unsigned g_bar_cnt = 0;
__device__ unsigned g_bar_gen = 0;

// ---------------- bf16 split helpers ----------------------------------------

DEV_INLINE void split2(float x0, float x1, uint32_t& hi, uint32_t& lo) {
    __nv_bfloat16 h0 = __float2bfloat16_rn(x0);
    __nv_bfloat16 h1 = __float2bfloat16_rn(x1);
    __nv_bfloat16 l0 = __float2bfloat16_rn(x0 - __bfloat162float(h0));
    __nv_bfloat16 l1 = __float2bfloat16_rn(x1 - __bfloat162float(h1));
    hi = (uint32_t)__bfloat16_as_ushort(h0) | ((uint32_t)__bfloat16_as_ushort(h1) << 16);
    lo = (uint32_t)__bfloat16_as_ushort(l0) | ((uint32_t)__bfloat16_as_ushort(l1) << 16);
}

// D += A(16x16, row) * B(16x8, col), bf16 in, fp32 accum
DEV_INLINE void mma16(float c[4], const uint32_t a[4], const uint32_t b[2]) {
    asm volatile(
        "mma.sync.aligned.m16n8k16.row.col.f32.bf16.bf16.f32 "
        "{%0,%1,%2,%3}, {%4,%5,%6,%7}, {%8,%9}, {%0,%1,%2,%3};\n"
        : "+f"(c[0]), "+f"(c[1]), "+f"(c[2]), "+f"(c[3])
        : "r"(a[0]), "r"(a[1]), "r"(a[2]), "r"(a[3]), "r"(b[0]), "r"(b[1]));
}

DEV_INLINE float sigmoidf_(float x) { return 1.0f / (1.0f + __expf(-x)); }

// ---------------- init: h0 = 0 ----------------------------------------------

__global__ void zero_h0_kernel() {
    int i = blockIdx.x * blockDim.x + threadIdx.x;
    if (i < kB * kDh) g_hs[i] = 0.0f;
    if (i < kB * kKP) g_hpk[i] = make_uint2(0u, 0u);
}

// ---------------- weight prep: pack h-part of Wz/Wr/Ws ----------------------
// g_wpk[((gate*kDh + j)*kKP) + kp] = split pair (W[2kp][j], W[2kp+1][j])

__global__ void prep_w_kernel(const float* __restrict__ Wz,
                              const float* __restrict__ Wr,
                              const float* __restrict__ Ws) {
    size_t i = (size_t)blockIdx.x * blockDim.x + threadIdx.x;
    if (i >= (size_t)3 * kKP * kDh) return;
    int j  = (int)(i & (kDh - 1));
    int kp = (int)((i >> 10) & (kKP - 1));
    int g  = (int)(i >> 19);
    const float* W = (g == 0) ? Wz : (g == 1) ? Wr : Ws;
    float x0 = W[(size_t)(2 * kp) * kDh + j];
    float x1 = W[(size_t)(2 * kp + 1) * kDh + j];
    uint32_t hi, lo;
    split2(x0, x1, hi, lo);
    g_wpk[((size_t)g * kDh + j) * kKP + kp] = make_uint2(hi, lo);
}

// ---------------- x-projections (bf16-split tiled GEMM) ---------------------
// C rows = b*T + t (32768), cols = 3*Dh gate-major. CTA = 64x64, 8 warps (4M x 2N).

__global__ void proj_x_kernel(const float* __restrict__ inp,
                              const float* __restrict__ Wz, const float* __restrict__ bz,
                              const float* __restrict__ Wr, const float* __restrict__ br,
                              const float* __restrict__ Ws, const float* __restrict__ bs) {
    const int r0   = blockIdx.x * 64;
    const int c0   = blockIdx.y * 64;
    const int gate = c0 >> 10;
    const int jg0  = c0 & (kDh - 1);
    const float* __restrict__ W    = (gate == 0) ? Wz : (gate == 1) ? Wr : Ws;
    const float* __restrict__ bias = (gate == 0) ? bz : (gate == 1) ? br : bs;

    __shared__ uint32_t Ah[64][17], Al[64][17];   // [m][kpair]
    __shared__ uint32_t Bh[64][17], Bl[64][17];   // [j][kpair]

    const int tid = threadIdx.x;
    const int wid = tid >> 5, lane = tid & 31;
    const int wm  = (wid & 3) * 16;
    const int wn  = (wid >> 2) * 32;
    const int grp = lane >> 2, tg = lane & 3;

    float acc[4][4] = {};

    for (int k0 = 0; k0 < kDin; k0 += 32) {
        // stage A pairs: 64 rows x 16 pairs
        for (int idx = tid; idx < 64 * 16; idx += 256) {
            int kp = idx >> 6;            // 0..15
            int m  = idx & 63;
            const float2 v = *reinterpret_cast<const float2*>(
                inp + (size_t)(r0 + m) * kDin + k0 + 2 * kp);
            split2(v.x, v.y, Ah[m][kp], Al[m][kp]);
        }
        // stage B pairs (transpose): 64 cols x 16 pairs
        for (int idx = tid; idx < 64 * 16; idx += 256) {
            int kp = idx >> 6;
            int j  = idx & 63;
            float x0 = W[(size_t)(kDh + k0 + 2 * kp) * kDh + jg0 + j];
            float x1 = W[(size_t)(kDh + k0 + 2 * kp + 1) * kDh + jg0 + j];
            split2(x0, x1, Bh[j][kp], Bl[j][kp]);
        }
        __syncthreads();
#pragma unroll
        for (int kt = 0; kt < 2; kt++) {
            uint32_t ah[4], al[4];
            ah[0] = Ah[wm + grp][kt * 8 + tg];         al[0] = Al[wm + grp][kt * 8 + tg];
            ah[1] = Ah[wm + grp + 8][kt * 8 + tg];     al[1] = Al[wm + grp + 8][kt * 8 + tg];
            ah[2] = Ah[wm + grp][kt * 8 + tg + 4];     al[2] = Al[wm + grp][kt * 8 + tg + 4];
            ah[3] = Ah[wm + grp + 8][kt * 8 + tg + 4]; al[3] = Al[wm + grp + 8][kt * 8 + tg + 4];
#pragma unroll
            for (int nt = 0; nt < 4; nt++) {
                const int jj = wn + nt * 8 + grp;
                uint32_t bh[2], bl[2];
                bh[0] = Bh[jj][kt * 8 + tg];     bl[0] = Bl[jj][kt * 8 + tg];
                bh[1] = Bh[jj][kt * 8 + tg + 4]; bl[1] = Bl[jj][kt * 8 + tg + 4];
                mma16(acc[nt], ah, bh);
                mma16(acc[nt], ah, bl);
                mma16(acc[nt], al, bh);
            }
        }
        __syncthreads();
    }

#pragma unroll
    for (int nt = 0; nt < 4; nt++) {
#pragma unroll
        for (int cc = 0; cc < 4; cc++) {
            int row = r0 + wm + grp + ((cc & 2) ? 8 : 0);   // = b*T + t
            int col = jg0 + wn + nt * 8 + 2 * tg + (cc & 1);
            int b = row >> 9;
            int t = row & (kT - 1);
            g_xbuf[(((size_t)t * 3 + gate) * kB + b) * kDh + col] = acc[nt][cc] + bias[col];
        }
    }
}

// ---------------- grid barrier (co-resident CTAs) ----------------------------

DEV_INLINE void grid_barrier() {
    __syncthreads();
    if (threadIdx.x == 0) {
        __threadfence();
        unsigned gen = *(volatile unsigned*)&g_bar_gen;
        if (atomicAdd(&g_bar_cnt, 1u) == kNC - 1u) {
            atomicExch(&g_bar_cnt, 0u);
            __threadfence();
            atomicExch(&g_bar_gen, gen + 1u);
        } else {
            while (*(volatile unsigned*)&g_bar_gen == gen) __nanosleep(32);
            __threadfence();
        }
    }
    __syncthreads();
}

// ---------------- GEMM core: one warp, m16 x (NT * n8), K = 1024 -------------
// A: packed pairs [64][kKP]; Bw: packed pairs [j][kKP] (pre-offset to j0).
// out[nt][4] = sum of hi*hi + hi*lo + lo*hi products.

template <int NT>
DEV_INLINE void gemm_wpk(const uint2* __restrict__ A, const uint2* __restrict__ Bw,
                         int j0, int wm, int grp, int tg, float out[NT][4]) {
    const uint2* __restrict__ a0p = A + (size_t)(wm + grp) * kKP;
    const uint2* __restrict__ a1p = A + (size_t)(wm + grp + 8) * kKP;
    const uint2* bp[NT];
#pragma unroll
    for (int nt = 0; nt < NT; nt++)
        bp[nt] = Bw + (size_t)(j0 + nt * 8 + grp) * kKP;

    float hh[NT][4], hl[NT][4], lh[NT][4];
#pragma unroll
    for (int nt = 0; nt < NT; nt++)
#pragma unroll
        for (int i = 0; i < 4; i++) { hh[nt][i] = 0.f; hl[nt][i] = 0.f; lh[nt][i] = 0.f; }

    uint2 a0 = a0p[tg], a1 = a1p[tg], a2 = a0p[tg + 4], a3 = a1p[tg + 4];
    uint2 b0[NT], b1[NT];
#pragma unroll
    for (int nt = 0; nt < NT; nt++) { b0[nt] = bp[nt][tg]; b1[nt] = bp[nt][tg + 4]; }

#pragma unroll 4
    for (int ks = 0; ks < kKP / 8; ks++) {
        uint2 na0, na1, na2, na3, nb0[NT], nb1[NT];
        if (ks < kKP / 8 - 1) {
            const int kp = (ks + 1) * 8;
            na0 = a0p[kp + tg]; na1 = a1p[kp + tg];
            na2 = a0p[kp + tg + 4]; na3 = a1p[kp + tg + 4];
#pragma unroll
            for (int nt = 0; nt < NT; nt++) { nb0[nt] = bp[nt][kp + tg]; nb1[nt] = bp[nt][kp + tg + 4]; }
        }
        const uint32_t ah[4] = {a0.x, a1.x, a2.x, a3.x};
        const uint32_t al[4] = {a0.y, a1.y, a2.y, a3.y};
#pragma unroll
        for (int nt = 0; nt < NT; nt++) {
            const uint32_t bh[2] = {b0[nt].x, b1[nt].x};
            const uint32_t bl[2] = {b0[nt].y, b1[nt].y};
            mma16(hh[nt], ah, bh);
            mma16(hl[nt], ah, bl);
            mma16(lh[nt], al, bh);
        }
        a0 = na0; a1 = na1; a2 = na2; a3 = na3;
#pragma unroll
        for (int nt = 0; nt < NT; nt++) { b0[nt] = nb0[nt]; b1[nt] = nb1[nt]; }
    }
#pragma unroll
    for (int nt = 0; nt < NT; nt++)
#pragma unroll
        for (int i = 0; i < 4; i++) out[nt][i] = hh[nt][i] + hl[nt][i] + lh[nt][i];
}

// ---------------- persistent recurrence kernel -------------------------------
// 64 CTAs x 256 threads (8 warps: 4 along M, 2 along N).
// Phase A: 2048 virtual cols (z: 0..1023 on CTAs 0..31, r: on CTAs 32..63),
//          32 cols/CTA, 16 cols per warp n-group (NT=2).
// Phase B: s gate, 16 cols/CTA (NT=1).

__global__ void __launch_bounds__(256, 1) recur_kernel() {
    const int c    = blockIdx.x;
    const int tid  = threadIdx.x;
    const int wid  = tid >> 5, lane = tid & 31;
    const int wm   = (wid & 3) * 16;
    const int wn8  = wid >> 2;
    const int grp  = lane >> 2, tg = lane & 3;

    const int gate = (c >= 32) ? 1 : 0;                 // A-phase gate for this CTA
    const int jA   = ((c & 31) * 32 + wn8 * 16);        // warp's col base, phase A (16 cols)
    const int jB   = (c * 16 + wn8 * 8);                // warp's col base, phase B (8 cols)

    const uint2* __restrict__ WA = g_wpk + (size_t)gate * kDh * kKP;
    const uint2* __restrict__ WB = g_wpk + (size_t)2 * kDh * kKP;

    for (int t = 0; t < kT; ++t) {
        // ---------- phase A: z or r ----------
        {
            float acc[2][4];
            gemm_wpk<2>(g_hpk, WA, jA, wm, grp, tg, acc);

            const float* __restrict__ xg = g_xbuf + ((size_t)t * 3 + gate) * kB * kDh;
            const float* __restrict__ hp = g_hs + (size_t)t * kB * kDh;
#pragma unroll
            for (int nt = 0; nt < 2; nt++) {
#pragma unroll
                for (int half = 0; half < 2; half++) {
                    const int b = wm + grp + half * 8;
                    const int j = jA + nt * 8 + 2 * tg;
                    const size_t o = (size_t)b * kDh + j;
                    const float s0 = acc[nt][2 * half + 0];
                    const float s1 = acc[nt][2 * half + 1];
                    if (gate == 0) {
                        g_z[o]     = sigmoidf_(s0 + xg[o]);
                        g_z[o + 1] = sigmoidf_(s1 + xg[o + 1]);
                    } else {
                        const float r0 = sigmoidf_(s0 + xg[o]);
                        const float r1 = sigmoidf_(s1 + xg[o + 1]);
                        uint32_t hi, lo;
                        split2(r0 * hp[o], r1 * hp[o + 1], hi, lo);
                        g_rhpk[(size_t)b * kKP + (j >> 1)] = make_uint2(hi, lo);
                    }
                }
            }
        }
        grid_barrier();

        // ---------- phase B: s gate + h update ----------
        {
            float acc[1][4];
            gemm_wpk<1>(g_rhpk, WB, jB, wm, grp, tg, acc);

            const float* __restrict__ xs = g_xbuf + ((size_t)t * 3 + 2) * kB * kDh;
            const float* __restrict__ hp = g_hs + (size_t)t * kB * kDh;
            float* __restrict__ hn       = g_hs + (size_t)(t + 1) * kB * kDh;
#pragma unroll
            for (int half = 0; half < 2; half++) {
                const int b = wm + grp + half * 8;
                const int j = jB + 2 * tg;
                const size_t o = (size_t)b * kDh + j;
                const float st0 = tanhf(acc[0][2 * half + 0] + xs[o]);
                const float st1 = tanhf(acc[0][2 * half + 1] + xs[o + 1]);
                const float h0 = hp[o], h1 = hp[o + 1];
                const float z0 = g_z[o], z1 = g_z[o + 1];
                const float v0 = fmaf(z0, st0 - h0, h0);
                const float v1 = fmaf(z1, st1 - h1, h1);
                *reinterpret_cast<float2*>(hn + o) = make_float2(v0, v1);
                uint32_t hi, lo;
                split2(v0, v1, hi, lo);
                g_hpk[(size_t)b * kKP + (j >> 1)] = make_uint2(hi, lo);
            }
        }
        grid_barrier();
    }
}

// ---------------- output projection: relu(hs @ Wo + bo) ----------------------

__global__ void out_proj_kernel(const float* __restrict__ Wo,
                                const float* __restrict__ bo,
                                float* __restrict__ out) {
    const int t  = blockIdx.x;
    const int c0 = blockIdx.y * 64;

    __shared__ uint32_t Ah[64][17], Al[64][17];
    __shared__ uint32_t Bh[64][17], Bl[64][17];

    const int tid = threadIdx.x;
    const int wid = tid >> 5, lane = tid & 31;
    const int wm  = (wid & 3) * 16;
    const int wn  = (wid >> 2) * 32;
    const int grp = lane >> 2, tg = lane & 3;

    const float* __restrict__ A = g_hs + (size_t)(t + 1) * kB * kDh;

    float acc[4][4] = {};

    for (int k0 = 0; k0 < kDh; k0 += 32) {
        for (int idx = tid; idx < 64 * 16; idx += 256) {
            int kp = idx >> 6;
            int m  = idx & 63;
            const float2 v = *reinterpret_cast<const float2*>(A + (size_t)m * kDh + k0 + 2 * kp);
            split2(v.x, v.y, Ah[m][kp], Al[m][kp]);
        }
        for (int idx = tid; idx < 64 * 16; idx += 256) {
            int kp = idx >> 6;
            int j  = idx & 63;
            float x0 = Wo[(size_t)(k0 + 2 * kp) * kDout + c0 + j];
            float x1 = Wo[(size_t)(k0 + 2 * kp + 1) * kDout + c0 + j];
            split2(x0, x1, Bh[j][kp], Bl[j][kp]);
        }
        __syncthreads();
#pragma unroll
        for (int kt = 0; kt < 2; kt++) {
            uint32_t ah[4], al[4];
            ah[0] = Ah[wm + grp][kt * 8 + tg];         al[0] = Al[wm + grp][kt * 8 + tg];
            ah[1] = Ah[wm + grp + 8][kt * 8 + tg];     al[1] = Al[wm + grp + 8][kt * 8 + tg];
            ah[2] = Ah[wm + grp][kt * 8 + tg + 4];     al[2] = Al[wm + grp][kt * 8 + tg + 4];
            ah[3] = Ah[wm + grp + 8][kt * 8 + tg + 4]; al[3] = Al[wm + grp + 8][kt * 8 + tg + 4];
#pragma unroll
            for (int nt = 0; nt < 4; nt++) {
                const int jj = wn + nt * 8 + grp;
                uint32_t bh[2], bl[2];
                bh[0] = Bh[jj][kt * 8 + tg];     bl[0] = Bl[jj][kt * 8 + tg];
                bh[1] = Bh[jj][kt * 8 + tg + 4]; bl[1] = Bl[jj][kt * 8 + tg + 4];
                mma16(acc[nt], ah, bh);
                mma16(acc[nt], ah, bl);
                mma16(acc[nt], al, bh);
            }
        }
        __syncthreads();
    }

#pragma unroll
    for (int nt = 0; nt < 4; nt++) {
#pragma unroll
        for (int cc = 0; cc < 4; cc++) {
            int b   = wm + grp + ((cc & 2) ? 8 : 0);
            int col = c0 + wn + nt * 8 + 2 * tg + (cc & 1);
            float v = acc[nt][cc] + bo[col];
            out[((size_t)b * kT + t) * kDout + col] = fmaxf(v, 0.0f);
        }
    }
}

// ---------------- h_final copy ----------------------------------------------

__global__ void final_copy_kernel(float* __restrict__ out) {
    int i = blockIdx.x * blockDim.x + threadIdx.x;
    if (i < kB * kDh)
        out[(size_t)kB * kT * kDout + i] = g_hs[(size_t)kT * kB * kDh + i];
}

// ---------------- launch ------------------------------------------------------
// d_in: inputs, Wz, bz, Wr, br, Ws, bs, Wo, bo ; d_out: [outputs | h_final] fp32

extern "C" void kernel_launch(void* const* d_in, const int* in_sizes, int n_in,
                              void* d_out, int out_size) {
    (void)in_sizes; (void)n_in; (void)out_size;
    const float* inp = (const float*)d_in[0];
    const float* Wz  = (const float*)d_in[1];
    const float* bz  = (const float*)d_in[2];
    const float* Wr  = (const float*)d_in[3];
    const float* br  = (const float*)d_in[4];
    const float* Ws  = (const float*)d_in[5];
    const float* bs  = (const float*)d_in[6];
    const float* Wo  = (const float*)d_in[7];
    const float* bo  = (const float*)d_in[8];
    float* out = (float*)d_out;

    zero_h0_kernel<<<(kB * kDh + 255) / 256, 256>>>();
    prep_w_kernel<<<(3 * kKP * kDh + 255) / 256, 256>>>(Wz, Wr, Ws);
    proj_x_kernel<<<dim3(kB * kT / 64, 3 * kDh / 64), 256>>>(inp, Wz, bz, Wr, br, Ws, bs);
    recur_kernel<<<kNC, 256>>>();
    out_proj_kernel<<<dim3(kT, kDout / 64), 256>>>(Wo, bo, out);
    final_copy_kernel<<<(kB * kDh + 255) / 256, 256>>>(out);
}

// round 8
// speedup vs baseline: 1.3814x; 1.3814x over previous
#include <cuda_runtime.h>
#include <cuda_bf16.h>
#include <cstdint>
#include <cstddef>

#define DEV_INLINE __device__ __forceinline__

namespace {
constexpr int kB    = 64;
constexpr int kT    = 512;
constexpr int kDin  = 512;
constexpr int kDh   = 1024;
constexpr int kDout = 1024;
constexpr int kNC   = 64;        // persistent CTA count (1 CTA/SM, co-resident)
constexpr int kKP   = kDh / 2;   // 512 k-pairs
constexpr int kKS   = kKP / 8;   // 64 k-chunks (16 elems each)
constexpr int CPA   = 33;        // padded col stride, phase A smem B (32 cols)
constexpr int CPB   = 17;        // padded col stride, phase B smem B (16 cols)
constexpr int kSmemA4 = kKS * 4 * CPA;              // uint4 count
constexpr int kSmemB4 = kKS * 4 * CPB;
constexpr size_t kSmemBytes = (size_t)(kSmemA4 + kSmemB4) * 16;  // 204800
}

// ---------------- device scratch (no allocs allowed) ------------------------
__device__ float g_xbuf[(size_t)kT * 3 * kB * kDh];   // [t][gate][b][j], x-proj + bias
__device__ float g_hs[(size_t)(kT + 1) * kB * kDh];   // [t][b][j]
__device__ float g_z[(size_t)kB * kDh];               // z gate (per step)
// packed operands, uint4 = { pk(8ks+q).hi, pk(8ks+q).lo, pk(8ks+q+4).hi, pk(8ks+q+4).lo }
// layout: [row b][ks][q]  (row stride = kKS*4 = 256 uint4)
__device__ uint4 g_hpk4[(size_t)kB * kKS * 4];
__device__ uint4 g_rhpk4[(size_t)kB * kKS * 4];
__device__ uint2 g_wpk[(size_t)3 * kDh * kKP];        // W*_h packed, [gate][j][kp]
__device__ unsigned g_bar_cnt = 0;
__device__ unsigned g_bar_gen = 0;

// ---------------- bf16 split helpers ----------------------------------------

DEV_INLINE void split2(float x0, float x1, uint32_t& hi, uint32_t& lo) {
    __nv_bfloat16 h0 = __float2bfloat16_rn(x0);
    __nv_bfloat16 h1 = __float2bfloat16_rn(x1);
    __nv_bfloat16 l0 = __float2bfloat16_rn(x0 - __bfloat162float(h0));
    __nv_bfloat16 l1 = __float2bfloat16_rn(x1 - __bfloat162float(h1));
    hi = (uint32_t)__bfloat16_as_ushort(h0) | ((uint32_t)__bfloat16_as_ushort(h1) << 16);
    lo = (uint32_t)__bfloat16_as_ushort(l0) | ((uint32_t)__bfloat16_as_ushort(l1) << 16);
}

// D += A(16x16, row) * B(16x8, col), bf16 in, fp32 accum
DEV_INLINE void mma16(float c[4], const uint32_t a[4], const uint32_t b[2]) {
    asm volatile(
        "mma.sync.aligned.m16n8k16.row.col.f32.bf16.bf16.f32 "
        "{%0,%1,%2,%3}, {%4,%5,%6,%7}, {%8,%9}, {%0,%1,%2,%3};\n"
        : "+f"(c[0]), "+f"(c[1]), "+f"(c[2]), "+f"(c[3])
        : "r"(a[0]), "r"(a[1]), "r"(a[2]), "r"(a[3]), "r"(b[0]), "r"(b[1]));
}

DEV_INLINE float sigmoidf_(float x) { return 1.0f / (1.0f + __expf(-x)); }

// ---------------- init -------------------------------------------------------

__global__ void zero_h0_kernel() {
    int i = blockIdx.x * blockDim.x + threadIdx.x;
    if (i < kB * kDh) g_hs[i] = 0.0f;
    if (i < kB * kKS * 4) g_hpk4[i] = make_uint4(0u, 0u, 0u, 0u);
}

// ---------------- weight prep: pack h-part of Wz/Wr/Ws ----------------------

__global__ void prep_w_kernel(const float* __restrict__ Wz,
                              const float* __restrict__ Wr,
                              const float* __restrict__ Ws) {
    size_t i = (size_t)blockIdx.x * blockDim.x + threadIdx.x;
    if (i >= (size_t)3 * kKP * kDh) return;
    int j  = (int)(i & (kDh - 1));
    int kp = (int)((i >> 10) & (kKP - 1));
    int g  = (int)(i >> 19);
    const float* W = (g == 0) ? Wz : (g == 1) ? Wr : Ws;
    float x0 = W[(size_t)(2 * kp) * kDh + j];
    float x1 = W[(size_t)(2 * kp + 1) * kDh + j];
    uint32_t hi, lo;
    split2(x0, x1, hi, lo);
    g_wpk[((size_t)g * kDh + j) * kKP + kp] = make_uint2(hi, lo);
}

// ---------------- x-projections (bf16-split tiled GEMM) ---------------------

__global__ void proj_x_kernel(const float* __restrict__ inp,
                              const float* __restrict__ Wz, const float* __restrict__ bz,
                              const float* __restrict__ Wr, const float* __restrict__ br,
                              const float* __restrict__ Ws, const float* __restrict__ bs) {
    const int r0   = blockIdx.x * 64;
    const int c0   = blockIdx.y * 64;
    const int gate = c0 >> 10;
    const int jg0  = c0 & (kDh - 1);
    const float* __restrict__ W    = (gate == 0) ? Wz : (gate == 1) ? Wr : Ws;
    const float* __restrict__ bias = (gate == 0) ? bz : (gate == 1) ? br : bs;

    __shared__ uint32_t Ah[64][17], Al[64][17];
    __shared__ uint32_t Bh[64][17], Bl[64][17];

    const int tid = threadIdx.x;
    const int wid = tid >> 5, lane = tid & 31;
    const int wm  = (wid & 3) * 16;
    const int wn  = (wid >> 2) * 32;
    const int grp = lane >> 2, tg = lane & 3;

    float acc[4][4] = {};

    for (int k0 = 0; k0 < kDin; k0 += 32) {
        for (int idx = tid; idx < 64 * 16; idx += 256) {
            int kp = idx >> 6;
            int m  = idx & 63;
            const float2 v = *reinterpret_cast<const float2*>(
                inp + (size_t)(r0 + m) * kDin + k0 + 2 * kp);
            split2(v.x, v.y, Ah[m][kp], Al[m][kp]);
        }
        for (int idx = tid; idx < 64 * 16; idx += 256) {
            int kp = idx >> 6;
            int j  = idx & 63;
            float x0 = W[(size_t)(kDh + k0 + 2 * kp) * kDh + jg0 + j];
            float x1 = W[(size_t)(kDh + k0 + 2 * kp + 1) * kDh + jg0 + j];
            split2(x0, x1, Bh[j][kp], Bl[j][kp]);
        }
        __syncthreads();
#pragma unroll
        for (int kt = 0; kt < 2; kt++) {
            uint32_t ah[4], al[4];
            ah[0] = Ah[wm + grp][kt * 8 + tg];         al[0] = Al[wm + grp][kt * 8 + tg];
            ah[1] = Ah[wm + grp + 8][kt * 8 + tg];     al[1] = Al[wm + grp + 8][kt * 8 + tg];
            ah[2] = Ah[wm + grp][kt * 8 + tg + 4];     al[2] = Al[wm + grp][kt * 8 + tg + 4];
            ah[3] = Ah[wm + grp + 8][kt * 8 + tg + 4]; al[3] = Al[wm + grp + 8][kt * 8 + tg + 4];
#pragma unroll
            for (int nt = 0; nt < 4; nt++) {
                const int jj = wn + nt * 8 + grp;
                uint32_t bh[2], bl[2];
                bh[0] = Bh[jj][kt * 8 + tg];     bl[0] = Bl[jj][kt * 8 + tg];
                bh[1] = Bh[jj][kt * 8 + tg + 4]; bl[1] = Bl[jj][kt * 8 + tg + 4];
                mma16(acc[nt], ah, bh);
                mma16(acc[nt], ah, bl);
                mma16(acc[nt], al, bh);
            }
        }
        __syncthreads();
    }

#pragma unroll
    for (int nt = 0; nt < 4; nt++) {
#pragma unroll
        for (int cc = 0; cc < 4; cc++) {
            int row = r0 + wm + grp + ((cc & 2) ? 8 : 0);
            int col = jg0 + wn + nt * 8 + 2 * tg + (cc & 1);
            int b = row >> 9;
            int t = row & (kT - 1);
            g_xbuf[(((size_t)t * 3 + gate) * kB + b) * kDh + col] = acc[nt][cc] + bias[col];
        }
    }
}

// ---------------- fast grid barrier (acquire/release) ------------------------

DEV_INLINE void grid_barrier() {
    __syncthreads();
    if (threadIdx.x == 0) {
        unsigned gen;
        asm volatile("ld.acquire.gpu.global.u32 %0, [%1];"
                     : "=r"(gen) : "l"(&g_bar_gen));
        unsigned old;
        asm volatile("atom.release.gpu.global.add.u32 %0, [%1], 1;"
                     : "=r"(old) : "l"(&g_bar_cnt));
        if (old == kNC - 1u) {
            asm volatile("st.relaxed.gpu.global.u32 [%0], 0;" :: "l"(&g_bar_cnt));
            asm volatile("st.release.gpu.global.u32 [%0], %1;"
                         :: "l"(&g_bar_gen), "r"(gen + 1u));
        } else {
            unsigned cur;
            do {
                asm volatile("ld.acquire.gpu.global.u32 %0, [%1];"
                             : "=r"(cur) : "l"(&g_bar_gen));
            } while (cur == gen);
        }
    }
    __syncthreads();
}

// ---------------- GEMM core: warp m16 x (NT*8), K=1024, B from smem ----------
// A4: [row][ks][q] uint4 (row stride 256). Bs: smem [(ks*4+q)*CPAD + j].

template <int NT, int CPAD>
DEV_INLINE void gemm_smem(const uint4* __restrict__ A4, const uint4* __restrict__ Bs,
                          int wm, int grp, int tg, float out[NT][4]) {
    const uint4* __restrict__ r0p = A4 + (size_t)(wm + grp) * (kKS * 4) + tg;
    const uint4* __restrict__ r1p = A4 + (size_t)(wm + grp + 8) * (kKS * 4) + tg;

    float hh[NT][4], hl[NT][4], lh[NT][4];
#pragma unroll
    for (int nt = 0; nt < NT; nt++)
#pragma unroll
        for (int i = 0; i < 4; i++) { hh[nt][i] = 0.f; hl[nt][i] = 0.f; lh[nt][i] = 0.f; }

    uint4 abuf[2][2];
    abuf[0][0] = r0p[0];  abuf[0][1] = r1p[0];
    abuf[1][0] = r0p[4];  abuf[1][1] = r1p[4];

#pragma unroll 4
    for (int ks = 0; ks < kKS; ks++) {
        const uint4 a0 = abuf[ks & 1][0];
        const uint4 a1 = abuf[ks & 1][1];
        if (ks + 2 < kKS) {
            abuf[ks & 1][0] = r0p[(ks + 2) * 4];
            abuf[ks & 1][1] = r1p[(ks + 2) * 4];
        }
        uint4 bq[NT];
        const uint4* __restrict__ brow = Bs + (ks * 4 + tg) * CPAD + grp;
#pragma unroll
        for (int nt = 0; nt < NT; nt++) bq[nt] = brow[nt * 8];

        const uint32_t ah[4] = {a0.x, a1.x, a0.z, a1.z};
        const uint32_t al[4] = {a0.y, a1.y, a0.w, a1.w};
#pragma unroll
        for (int nt = 0; nt < NT; nt++) {
            const uint32_t bh[2] = {bq[nt].x, bq[nt].z};
            const uint32_t bl[2] = {bq[nt].y, bq[nt].w};
            mma16(hh[nt], ah, bh);
            mma16(hl[nt], ah, bl);
            mma16(lh[nt], al, bh);
        }
    }
#pragma unroll
    for (int nt = 0; nt < NT; nt++)
#pragma unroll
        for (int i = 0; i < 4; i++) out[nt][i] = hh[nt][i] + hl[nt][i] + lh[nt][i];
}

// write packed pair (uint2) for k-pair kp of row b into a [row][ks][q] uint4 array
DEV_INLINE void store_pk(uint4* arr, int b, int kp, uint32_t hi, uint32_t lo) {
    int ks = kp >> 3, q = kp & 3, half = (kp >> 2) & 1;
    uint2* p = reinterpret_cast<uint2*>(arr + ((size_t)b * kKS + ks) * 4 + q) + half;
    *p = make_uint2(hi, lo);
}

// ---------------- persistent recurrence kernel -------------------------------
// 64 CTAs x 128 threads (4 warps along M=64).
// Phase A: CTAs 0..31 -> z cols 32c..32c+31 ; CTAs 32..63 -> r cols (NT=4).
// Phase B: CTA c -> s cols 16c..16c+15 (NT=2).

__global__ void __launch_bounds__(128, 1) recur_kernel() {
    extern __shared__ uint4 smem[];
    uint4* smemA = smem;                 // [(ks*4+q)*CPA + j], 32 cols
    uint4* smemB = smem + kSmemA4;       // [(ks*4+q)*CPB + j], 16 cols

    const int c    = blockIdx.x;
    const int tid  = threadIdx.x;
    const int wid  = tid >> 5, lane = tid & 31;
    const int wm   = wid * 16;
    const int grp  = lane >> 2, tg = lane & 3;

    const int gate = (c >= 32) ? 1 : 0;
    const int jA   = (c & 31) * 32;
    const int jB   = c * 16;

    // ---- prolog: load this CTA's weight slices into smem (once) ----
    {
        const uint2* __restrict__ wa = g_wpk + ((size_t)gate * kDh + jA) * kKP;
        for (int idx = tid; idx < 32 * kKP; idx += 128) {
            int j = idx >> 9, kp = idx & (kKP - 1);
            uint2 v = wa[(size_t)j * kKP + kp];
            int ks = kp >> 3, q = kp & 3, half = (kp >> 2) & 1;
            uint2* p = reinterpret_cast<uint2*>(&smemA[(ks * 4 + q) * CPA + j]) + half;
            *p = v;
        }
        const uint2* __restrict__ wb = g_wpk + ((size_t)2 * kDh + jB) * kKP;
        for (int idx = tid; idx < 16 * kKP; idx += 128) {
            int j = idx >> 9, kp = idx & (kKP - 1);
            uint2 v = wb[(size_t)j * kKP + kp];
            int ks = kp >> 3, q = kp & 3, half = (kp >> 2) & 1;
            uint2* p = reinterpret_cast<uint2*>(&smemB[(ks * 4 + q) * CPB + j]) + half;
            *p = v;
        }
        __syncthreads();
    }

    for (int t = 0; t < kT; ++t) {
        // ---------- phase A: z (CTAs 0..31) or r (CTAs 32..63) ----------
        {
            const float* __restrict__ xg = g_xbuf + ((size_t)t * 3 + gate) * kB * kDh;
            const float* __restrict__ hp = g_hs + (size_t)t * kB * kDh;

            float2 xv[4][2], hv[4][2];
#pragma unroll
            for (int nt = 0; nt < 4; nt++)
#pragma unroll
                for (int half = 0; half < 2; half++) {
                    const int b = wm + grp + half * 8;
                    const int j = jA + nt * 8 + 2 * tg;
                    xv[nt][half] = *reinterpret_cast<const float2*>(xg + (size_t)b * kDh + j);
                    if (gate)
                        hv[nt][half] = *reinterpret_cast<const float2*>(hp + (size_t)b * kDh + j);
                }

            float acc[4][4];
            gemm_smem<4, CPA>(g_hpk4, smemA, wm, grp, tg, acc);

#pragma unroll
            for (int nt = 0; nt < 4; nt++)
#pragma unroll
                for (int half = 0; half < 2; half++) {
                    const int b = wm + grp + half * 8;
                    const int j = jA + nt * 8 + 2 * tg;
                    const float g0 = sigmoidf_(acc[nt][2 * half + 0] + xv[nt][half].x);
                    const float g1 = sigmoidf_(acc[nt][2 * half + 1] + xv[nt][half].y);
                    if (gate == 0) {
                        *reinterpret_cast<float2*>(g_z + (size_t)b * kDh + j) =
                            make_float2(g0, g1);
                    } else {
                        uint32_t hi, lo;
                        split2(g0 * hv[nt][half].x, g1 * hv[nt][half].y, hi, lo);
                        store_pk(g_rhpk4, b, j >> 1, hi, lo);
                    }
                }
        }
        grid_barrier();

        // ---------- phase B: s gate + h update ----------
        {
            const float* __restrict__ xs = g_xbuf + ((size_t)t * 3 + 2) * kB * kDh;
            const float* __restrict__ hp = g_hs + (size_t)t * kB * kDh;
            float* __restrict__ hn       = g_hs + (size_t)(t + 1) * kB * kDh;

            float2 xv[2][2], hv[2][2], zv[2][2];
#pragma unroll
            for (int nt = 0; nt < 2; nt++)
#pragma unroll
                for (int half = 0; half < 2; half++) {
                    const int b = wm + grp + half * 8;
                    const int j = jB + nt * 8 + 2 * tg;
                    const size_t o = (size_t)b * kDh + j;
                    xv[nt][half] = *reinterpret_cast<const float2*>(xs + o);
                    hv[nt][half] = *reinterpret_cast<const float2*>(hp + o);
                    zv[nt][half] = *reinterpret_cast<const float2*>(g_z + o);
                }

            float acc[2][4];
            gemm_smem<2, CPB>(g_rhpk4, smemB, wm, grp, tg, acc);

#pragma unroll
            for (int nt = 0; nt < 2; nt++)
#pragma unroll
                for (int half = 0; half < 2; half++) {
                    const int b = wm + grp + half * 8;
                    const int j = jB + nt * 8 + 2 * tg;
                    const size_t o = (size_t)b * kDh + j;
                    const float st0 = tanhf(acc[nt][2 * half + 0] + xv[nt][half].x);
                    const float st1 = tanhf(acc[nt][2 * half + 1] + xv[nt][half].y);
                    const float h0 = hv[nt][half].x, h1 = hv[nt][half].y;
                    const float v0 = fmaf(zv[nt][half].x, st0 - h0, h0);
                    const float v1 = fmaf(zv[nt][half].y, st1 - h1, h1);
                    *reinterpret_cast<float2*>(hn + o) = make_float2(v0, v1);
                    uint32_t hi, lo;
                    split2(v0, v1, hi, lo);
                    store_pk(g_hpk4, b, j >> 1, hi, lo);
                }
        }
        grid_barrier();
    }
}

// ---------------- output projection: relu(hs @ Wo + bo) ----------------------

__global__ void out_proj_kernel(const float* __restrict__ Wo,
                                const float* __restrict__ bo,
                                float* __restrict__ out) {
    const int t  = blockIdx.x;
    const int c0 = blockIdx.y * 64;

    __shared__ uint32_t Ah[64][17], Al[64][17];
    __shared__ uint32_t Bh[64][17], Bl[64][17];

    const int tid = threadIdx.x;
    const int wid = tid >> 5, lane = tid & 31;
    const int wm  = (wid & 3) * 16;
    const int wn  = (wid >> 2) * 32;
    const int grp = lane >> 2, tg = lane & 3;

    const float* __restrict__ A = g_hs + (size_t)(t + 1) * kB * kDh;

    float acc[4][4] = {};

    for (int k0 = 0; k0 < kDh; k0 += 32) {
        for (int idx = tid; idx < 64 * 16; idx += 256) {
            int kp = idx >> 6;
            int m  = idx & 63;
            const float2 v = *reinterpret_cast<const float2*>(A + (size_t)m * kDh + k0 + 2 * kp);
            split2(v.x, v.y, Ah[m][kp], Al[m][kp]);
        }
        for (int idx = tid; idx < 64 * 16; idx += 256) {
            int kp = idx >> 6;
            int j  = idx & 63;
            float x0 = Wo[(size_t)(k0 + 2 * kp) * kDout + c0 + j];
            float x1 = Wo[(size_t)(k0 + 2 * kp + 1) * kDout + c0 + j];
            split2(x0, x1, Bh[j][kp], Bl[j][kp]);
        }
        __syncthreads();
#pragma unroll
        for (int kt = 0; kt < 2; kt++) {
            uint32_t ah[4], al[4];
            ah[0] = Ah[wm + grp][kt * 8 + tg];         al[0] = Al[wm + grp][kt * 8 + tg];
            ah[1] = Ah[wm + grp + 8][kt * 8 + tg];     al[1] = Al[wm + grp + 8][kt * 8 + tg];
            ah[2] = Ah[wm + grp][kt * 8 + tg + 4];     al[2] = Al[wm + grp][kt * 8 + tg + 4];
            ah[3] = Ah[wm + grp + 8][kt * 8 + tg + 4]; al[3] = Al[wm + grp + 8][kt * 8 + tg + 4];
#pragma unroll
            for (int nt = 0; nt < 4; nt++) {
                const int jj = wn + nt * 8 + grp;
                uint32_t bh[2], bl[2];
                bh[0] = Bh[jj][kt * 8 + tg];     bl[0] = Bl[jj][kt * 8 + tg];
                bh[1] = Bh[jj][kt * 8 + tg + 4]; bl[1] = Bl[jj][kt * 8 + tg + 4];
                mma16(acc[nt], ah, bh);
                mma16(acc[nt], ah, bl);
                mma16(acc[nt], al, bh);
            }
        }
        __syncthreads();
    }

#pragma unroll
    for (int nt = 0; nt < 4; nt++) {
#pragma unroll
        for (int cc = 0; cc < 4; cc++) {
            int b   = wm + grp + ((cc & 2) ? 8 : 0);
            int col = c0 + wn + nt * 8 + 2 * tg + (cc & 1);
            float v = acc[nt][cc] + bo[col];
            out[((size_t)b * kT + t) * kDout + col] = fmaxf(v, 0.0f);
        }
    }
}

// ---------------- h_final copy ----------------------------------------------

__global__ void final_copy_kernel(float* __restrict__ out) {
    int i = blockIdx.x * blockDim.x + threadIdx.x;
    if (i < kB * kDh)
        out[(size_t)kB * kT * kDout + i] = g_hs[(size_t)kT * kB * kDh + i];
}

// ---------------- launch ------------------------------------------------------
// d_in: inputs, Wz, bz, Wr, br, Ws, bs, Wo, bo ; d_out: [outputs | h_final] fp32

extern "C" void kernel_launch(void* const* d_in, const int* in_sizes, int n_in,
                              void* d_out, int out_size) {
    (void)in_sizes; (void)n_in; (void)out_size;
    const float* inp = (const float*)d_in[0];
    const float* Wz  = (const float*)d_in[1];
    const float* bz  = (const float*)d_in[2];
    const float* Wr  = (const float*)d_in[3];
    const float* br  = (const float*)d_in[4];
    const float* Ws  = (const float*)d_in[5];
    const float* bs  = (const float*)d_in[6];
    const float* Wo  = (const float*)d_in[7];
    const float* bo  = (const float*)d_in[8];
    float* out = (float*)d_out;

    cudaFuncSetAttribute(recur_kernel, cudaFuncAttributeMaxDynamicSharedMemorySize,
                         (int)kSmemBytes);

    zero_h0_kernel<<<(kB * kDh + 255) / 256, 256>>>();
    prep_w_kernel<<<(3 * kKP * kDh + 255) / 256, 256>>>(Wz, Wr, Ws);
    proj_x_kernel<<<dim3(kB * kT / 64, 3 * kDh / 64), 256>>>(inp, Wz, bz, Wr, br, Ws, bs);
    recur_kernel<<<kNC, 128, kSmemBytes>>>();
    out_proj_kernel<<<dim3(kT, kDout / 64), 256>>>(Wo, bo, out);
    final_copy_kernel<<<(kB * kDh + 255) / 256, 256>>>(out);
}

// round 10
// speedup vs baseline: 1.9412x; 1.4053x over previous
#include <cuda_runtime.h>
#include <cuda_bf16.h>
#include <cstdint>
#include <cstddef>

#define DEV_INLINE __device__ __forceinline__

namespace {
constexpr int kB    = 64;
constexpr int kT    = 512;
constexpr int kDin  = 512;
constexpr int kDh   = 1024;
constexpr int kDout = 1024;
constexpr int kNC   = 64;        // persistent CTA count (1 CTA/SM, co-resident)
constexpr int kKP   = kDh / 2;   // 512 k-pairs (recurrent K)
constexpr int kKPx  = kDin / 2;  // 256 k-pairs (input K)
constexpr int kKS   = kKP / 8;   // 64 k-chunks (16 elems each)
constexpr int CPA   = 33;        // padded col stride, phase A smem B (32 cols)
constexpr int CPB   = 17;        // padded col stride, phase B smem B (16 cols)
constexpr int kSmemA4 = kKS * 4 * CPA;              // uint4 count
constexpr int kSmemB4 = kKS * 4 * CPB;
constexpr int kRedFloats = 4 * 16 * 32;             // reduction buffer
constexpr size_t kSmemBytes = (size_t)(kSmemA4 + kSmemB4) * 16 + kRedFloats * 4; // 212992
}

// ---------------- device scratch (no allocs allowed) ------------------------
__device__ float g_xbuf[(size_t)kT * 3 * kB * kDh];   // [t][gate][b][j], x-proj + bias
__device__ float g_hs[(size_t)(kT + 1) * kB * kDh];   // [t][b][j]
__device__ float g_z[(size_t)kB * kDh];               // z gate (per step)
// packed GEMM-A operands, uint4 = { pk(8ks+q).hi, .lo, pk(8ks+q+4).hi, .lo }
__device__ uint4 g_hpk4[(size_t)kB * kKS * 4];        // current h packed (ring)
__device__ uint4 g_rhpk4[(size_t)kB * kKS * 4];       // r*h packed
__device__ uint2 g_wpk[(size_t)3 * kDh * kKP];        // W*_h packed, [gate][j][kp]
// pre-packed operands for the parallel GEMMs
__device__ uint2 g_inpk[(size_t)kB * kT * kKPx];      // inputs packed [row=b*T+t][kp]
__device__ uint2 g_wxpk[(size_t)3 * kDh * kKPx];      // W*_x packed [gate][j][kp]
__device__ uint2 g_wopk[(size_t)kDout * kKP];         // Wo packed [o][kp]
__device__ uint2 g_hspk[(size_t)kT * kB * kKP];       // h history packed [t][b][kp]
__device__ unsigned g_bar_cnt = 0;
__device__ unsigned g_bar_gen = 0;

// ---------------- bf16 split helpers ----------------------------------------

DEV_INLINE void split2(float x0, float x1, uint32_t& hi, uint32_t& lo) {
    __nv_bfloat16 h0 = __float2bfloat16_rn(x0);
    __nv_bfloat16 h1 = __float2bfloat16_rn(x1);
    __nv_bfloat16 l0 = __float2bfloat16_rn(x0 - __bfloat162float(h0));
    __nv_bfloat16 l1 = __float2bfloat16_rn(x1 - __bfloat162float(h1));
    hi = (uint32_t)__bfloat16_as_ushort(h0) | ((uint32_t)__bfloat16_as_ushort(h1) << 16);
    lo = (uint32_t)__bfloat16_as_ushort(l0) | ((uint32_t)__bfloat16_as_ushort(l1) << 16);
}

// D += A(16x16, row) * B(16x8, col), bf16 in, fp32 accum
DEV_INLINE void mma16(float c[4], const uint32_t a[4], const uint32_t b[2]) {
    asm volatile(
        "mma.sync.aligned.m16n8k16.row.col.f32.bf16.bf16.f32 "
        "{%0,%1,%2,%3}, {%4,%5,%6,%7}, {%8,%9}, {%0,%1,%2,%3};\n"
        : "+f"(c[0]), "+f"(c[1]), "+f"(c[2]), "+f"(c[3])
        : "r"(a[0]), "r"(a[1]), "r"(a[2]), "r"(a[3]), "r"(b[0]), "r"(b[1]));
}

DEV_INLINE float sigmoidf_(float x) { return 1.0f / (1.0f + __expf(-x)); }

// ---------------- init -------------------------------------------------------

__global__ void zero_h0_kernel() {
    int i = blockIdx.x * blockDim.x + threadIdx.x;
    if (i < kB * kDh) g_hs[i] = 0.0f;
    if (i < kB * kKS * 4) g_hpk4[i] = make_uint4(0u, 0u, 0u, 0u);
}

// ---------------- packers ----------------------------------------------------

__global__ void prep_w_kernel(const float* __restrict__ Wz,
                              const float* __restrict__ Wr,
                              const float* __restrict__ Ws) {
    size_t i = (size_t)blockIdx.x * blockDim.x + threadIdx.x;
    if (i >= (size_t)3 * kKP * kDh) return;
    int j  = (int)(i & (kDh - 1));
    int kp = (int)((i >> 10) & (kKP - 1));
    int g  = (int)(i >> 19);
    const float* W = (g == 0) ? Wz : (g == 1) ? Wr : Ws;
    uint32_t hi, lo;
    split2(W[(size_t)(2 * kp) * kDh + j], W[(size_t)(2 * kp + 1) * kDh + j], hi, lo);
    g_wpk[((size_t)g * kDh + j) * kKP + kp] = make_uint2(hi, lo);
}

__global__ void prep_wx_kernel(const float* __restrict__ Wz,
                               const float* __restrict__ Wr,
                               const float* __restrict__ Ws) {
    size_t i = (size_t)blockIdx.x * blockDim.x + threadIdx.x;
    if (i >= (size_t)3 * kDh * kKPx) return;
    int kp = (int)(i & (kKPx - 1));
    int j  = (int)((i >> 8) & (kDh - 1));
    int g  = (int)(i >> 18);
    const float* W = (g == 0) ? Wz : (g == 1) ? Wr : Ws;
    uint32_t hi, lo;
    split2(W[(size_t)(kDh + 2 * kp) * kDh + j],
           W[(size_t)(kDh + 2 * kp + 1) * kDh + j], hi, lo);
    g_wxpk[((size_t)g * kDh + j) * kKPx + kp] = make_uint2(hi, lo);
}

__global__ void prep_wo_kernel(const float* __restrict__ Wo) {
    size_t i = (size_t)blockIdx.x * blockDim.x + threadIdx.x;
    if (i >= (size_t)kDout * kKP) return;
    int kp = (int)(i & (kKP - 1));
    int o  = (int)(i >> 9);
    uint32_t hi, lo;
    split2(Wo[(size_t)(2 * kp) * kDout + o], Wo[(size_t)(2 * kp + 1) * kDout + o], hi, lo);
    g_wopk[(size_t)o * kKP + kp] = make_uint2(hi, lo);
}

__global__ void prep_in_kernel(const float* __restrict__ inp) {
    size_t i = (size_t)blockIdx.x * blockDim.x + threadIdx.x;
    if (i >= (size_t)kB * kT * kKPx) return;
    const float2 v = *reinterpret_cast<const float2*>(inp + 2 * i);
    uint32_t hi, lo;
    split2(v.x, v.y, hi, lo);
    g_inpk[i] = make_uint2(hi, lo);
}

// ---------------- x-projections (packed operands, pure GEMM) -----------------
// C rows = b*T + t (32768), cols = 3*Dh gate-major. CTA = 64x64, 8 warps (4M x 2N).

__global__ void proj_x_kernel(const float* __restrict__ bz,
                              const float* __restrict__ br,
                              const float* __restrict__ bs) {
    const int r0   = blockIdx.x * 64;
    const int c0   = blockIdx.y * 64;
    const int gate = c0 >> 10;
    const int jg0  = c0 & (kDh - 1);
    const float* __restrict__ bias = (gate == 0) ? bz : (gate == 1) ? br : bs;

    __shared__ uint32_t Ah[64][17], Al[64][17];
    __shared__ uint32_t Bh[64][17], Bl[64][17];

    const int tid = threadIdx.x;
    const int wid = tid >> 5, lane = tid & 31;
    const int wm  = (wid & 3) * 16;
    const int wn  = (wid >> 2) * 32;
    const int grp = lane >> 2, tg = lane & 3;

    const uint2* __restrict__ Bw = g_wxpk + (size_t)gate * kDh * kKPx;

    float acc[4][4] = {};

    for (int kp0 = 0; kp0 < kKPx; kp0 += 16) {
        for (int idx = tid; idx < 64 * 16; idx += 256) {
            int kp = idx & 15, m = idx >> 4;
            uint2 v = g_inpk[(size_t)(r0 + m) * kKPx + kp0 + kp];
            Ah[m][kp] = v.x; Al[m][kp] = v.y;
        }
        for (int idx = tid; idx < 64 * 16; idx += 256) {
            int kp = idx & 15, j = idx >> 4;
            uint2 v = Bw[(size_t)(jg0 + j) * kKPx + kp0 + kp];
            Bh[j][kp] = v.x; Bl[j][kp] = v.y;
        }
        __syncthreads();
#pragma unroll
        for (int kt = 0; kt < 2; kt++) {
            uint32_t ah[4], al[4];
            ah[0] = Ah[wm + grp][kt * 8 + tg];         al[0] = Al[wm + grp][kt * 8 + tg];
            ah[1] = Ah[wm + grp + 8][kt * 8 + tg];     al[1] = Al[wm + grp + 8][kt * 8 + tg];
            ah[2] = Ah[wm + grp][kt * 8 + tg + 4];     al[2] = Al[wm + grp][kt * 8 + tg + 4];
            ah[3] = Ah[wm + grp + 8][kt * 8 + tg + 4]; al[3] = Al[wm + grp + 8][kt * 8 + tg + 4];
#pragma unroll
            for (int nt = 0; nt < 4; nt++) {
                const int jj = wn + nt * 8 + grp;
                uint32_t bh[2], bl[2];
                bh[0] = Bh[jj][kt * 8 + tg];     bl[0] = Bl[jj][kt * 8 + tg];
                bh[1] = Bh[jj][kt * 8 + tg + 4]; bl[1] = Bl[jj][kt * 8 + tg + 4];
                mma16(acc[nt], ah, bh);
                mma16(acc[nt], ah, bl);
                mma16(acc[nt], al, bh);
            }
        }
        __syncthreads();
    }

#pragma unroll
    for (int nt = 0; nt < 4; nt++) {
#pragma unroll
        for (int cc = 0; cc < 4; cc++) {
            int row = r0 + wm + grp + ((cc & 2) ? 8 : 0);
            int col = jg0 + wn + nt * 8 + 2 * tg + (cc & 1);
            int b = row >> 9;
            int t = row & (kT - 1);
            g_xbuf[(((size_t)t * 3 + gate) * kB + b) * kDh + col] = acc[nt][cc] + bias[col];
        }
    }
}

// ---------------- fast grid barrier (acquire/release) ------------------------

DEV_INLINE void grid_barrier() {
    __syncthreads();
    if (threadIdx.x == 0) {
        unsigned gen;
        asm volatile("ld.acquire.gpu.global.u32 %0, [%1];"
                     : "=r"(gen) : "l"(&g_bar_gen));
        unsigned old;
        asm volatile("atom.release.gpu.global.add.u32 %0, [%1], 1;"
                     : "=r"(old) : "l"(&g_bar_cnt));
        if (old == kNC - 1u) {
            asm volatile("st.relaxed.gpu.global.u32 [%0], 0;" :: "l"(&g_bar_cnt));
            asm volatile("st.release.gpu.global.u32 [%0], %1;"
                         :: "l"(&g_bar_gen), "r"(gen + 1u));
        } else {
            unsigned cur;
            do {
                asm volatile("ld.acquire.gpu.global.u32 %0, [%1];"
                             : "=r"(cur) : "l"(&g_bar_gen));
            } while (cur == gen);
        }
    }
    __syncthreads();
}

// ---------------- GEMM core: warp m16 x (NT*8), 32 k-chunks, B from smem -----
// A4: [row][ks][q] uint4 (row stride kKS*4). Bs: smem [(ks*4+q)*CPAD + j].

template <int NT, int CPAD>
DEV_INLINE void gemm_smem(const uint4* __restrict__ A4, const uint4* __restrict__ Bs,
                          int ks0, int wm, int grp, int tg, float out[NT][4]) {
    const uint4* __restrict__ r0p = A4 + (size_t)(wm + grp) * (kKS * 4) + tg;
    const uint4* __restrict__ r1p = A4 + (size_t)(wm + grp + 8) * (kKS * 4) + tg;

    float hh[NT][4], hl[NT][4], lh[NT][4];
#pragma unroll
    for (int nt = 0; nt < NT; nt++)
#pragma unroll
        for (int i = 0; i < 4; i++) { hh[nt][i] = 0.f; hl[nt][i] = 0.f; lh[nt][i] = 0.f; }

    uint4 abuf[2][2];
    abuf[0][0] = r0p[ks0 * 4];        abuf[0][1] = r1p[ks0 * 4];
    abuf[1][0] = r0p[(ks0 + 1) * 4];  abuf[1][1] = r1p[(ks0 + 1) * 4];

#pragma unroll 4
    for (int s = 0; s < 32; s++) {
        const int ks = ks0 + s;
        const uint4 a0 = abuf[s & 1][0];
        const uint4 a1 = abuf[s & 1][1];
        if (s + 2 < 32) {
            abuf[s & 1][0] = r0p[(ks + 2) * 4];
            abuf[s & 1][1] = r1p[(ks + 2) * 4];
        }
        uint4 bq[NT];
        const uint4* __restrict__ brow = Bs + (ks * 4 + tg) * CPAD + grp;
#pragma unroll
        for (int nt = 0; nt < NT; nt++) bq[nt] = brow[nt * 8];

        const uint32_t ah[4] = {a0.x, a1.x, a0.z, a1.z};
        const uint32_t al[4] = {a0.y, a1.y, a0.w, a1.w};
#pragma unroll
        for (int nt = 0; nt < NT; nt++) {
            const uint32_t bh[2] = {bq[nt].x, bq[nt].z};
            const uint32_t bl[2] = {bq[nt].y, bq[nt].w};
            mma16(hh[nt], ah, bh);
            mma16(hl[nt], ah, bl);
            mma16(lh[nt], al, bh);
        }
    }
#pragma unroll
    for (int nt = 0; nt < NT; nt++)
#pragma unroll
        for (int i = 0; i < 4; i++) out[nt][i] = hh[nt][i] + hl[nt][i] + lh[nt][i];
}

// write packed pair (uint2) for k-pair kp of row b into a [row][ks][q] uint4 array
DEV_INLINE void store_pk(uint4* arr, int b, int kp, uint32_t hi, uint32_t lo) {
    int ks = kp >> 3, q = kp & 3, half = (kp >> 2) & 1;
    uint2* p = reinterpret_cast<uint2*>(arr + ((size_t)b * kKS + ks) * 4 + q) + half;
    *p = make_uint2(hi, lo);
}

// ---------------- persistent recurrence kernel -------------------------------
// 64 CTAs x 256 threads. Warp = (mq = wid&3 -> 16-row block, kh = wid>>2 -> K half).
// Phase A: CTAs 0..31 -> z cols 32c..32c+31; CTAs 32..63 -> r cols (NT=4).
// Phase B: CTA c -> s cols 16c..16c+15 (NT=2). Cross-K reduction in smem.

__global__ void __launch_bounds__(256, 1) recur_kernel() {
    extern __shared__ uint4 smem[];
    uint4* smemA = smem;                       // 32 cols
    uint4* smemB = smem + kSmemA4;             // 16 cols
    float* red   = reinterpret_cast<float*>(smem + kSmemA4 + kSmemB4);

    const int c    = blockIdx.x;
    const int tid  = threadIdx.x;
    const int wid  = tid >> 5, lane = tid & 31;
    const int mq   = wid & 3, kh = wid >> 2;
    const int wm   = mq * 16;
    const int ks0  = kh * 32;
    const int grp  = lane >> 2, tg = lane & 3;

    const int gate = (c >= 32) ? 1 : 0;
    const int jA   = (c & 31) * 32;
    const int jB   = c * 16;

    // ---- prolog: load this CTA's weight slices into smem (once) ----
    {
        const uint2* __restrict__ wa = g_wpk + ((size_t)gate * kDh + jA) * kKP;
        for (int idx = tid; idx < 32 * kKP; idx += 256) {
            int j = idx >> 9, kp = idx & (kKP - 1);
            uint2 v = wa[(size_t)j * kKP + kp];
            int ks = kp >> 3, q = kp & 3, half = (kp >> 2) & 1;
            uint2* p = reinterpret_cast<uint2*>(&smemA[(ks * 4 + q) * CPA + j]) + half;
            *p = v;
        }
        const uint2* __restrict__ wb = g_wpk + ((size_t)2 * kDh + jB) * kKP;
        for (int idx = tid; idx < 16 * kKP; idx += 256) {
            int j = idx >> 9, kp = idx & (kKP - 1);
            uint2 v = wb[(size_t)j * kKP + kp];
            int ks = kp >> 3, q = kp & 3, half = (kp >> 2) & 1;
            uint2* p = reinterpret_cast<uint2*>(&smemB[(ks * 4 + q) * CPB + j]) + half;
            *p = v;
        }
        __syncthreads();
    }

    for (int t = 0; t < kT; ++t) {
        // ---------- phase A: z (CTAs 0..31) or r (CTAs 32..63) ----------
        {
            const float* __restrict__ xg = g_xbuf + ((size_t)t * 3 + gate) * kB * kDh;
            const float* __restrict__ hp = g_hs + (size_t)t * kB * kDh;

            float2 xv[4][2], hv[4][2];
            if (kh == 0) {
#pragma unroll
                for (int nt = 0; nt < 4; nt++)
#pragma unroll
                    for (int half = 0; half < 2; half++) {
                        const int b = wm + grp + half * 8;
                        const int j = jA + nt * 8 + 2 * tg;
                        xv[nt][half] = *reinterpret_cast<const float2*>(xg + (size_t)b * kDh + j);
                        if (gate)
                            hv[nt][half] = *reinterpret_cast<const float2*>(hp + (size_t)b * kDh + j);
                    }
            }

            float acc[4][4];
            gemm_smem<4, CPA>(g_hpk4, smemA, ks0, wm, grp, tg, acc);

            if (kh == 1) {
#pragma unroll
                for (int nt = 0; nt < 4; nt++)
#pragma unroll
                    for (int i = 0; i < 4; i++)
                        red[(mq * 16 + nt * 4 + i) * 32 + lane] = acc[nt][i];
            }
            __syncthreads();
            if (kh == 0) {
#pragma unroll
                for (int nt = 0; nt < 4; nt++)
#pragma unroll
                    for (int i = 0; i < 4; i++)
                        acc[nt][i] += red[(mq * 16 + nt * 4 + i) * 32 + lane];
#pragma unroll
                for (int nt = 0; nt < 4; nt++)
#pragma unroll
                    for (int half = 0; half < 2; half++) {
                        const int b = wm + grp + half * 8;
                        const int j = jA + nt * 8 + 2 * tg;
                        const float g0 = sigmoidf_(acc[nt][2 * half + 0] + xv[nt][half].x);
                        const float g1 = sigmoidf_(acc[nt][2 * half + 1] + xv[nt][half].y);
                        if (gate == 0) {
                            *reinterpret_cast<float2*>(g_z + (size_t)b * kDh + j) =
                                make_float2(g0, g1);
                        } else {
                            uint32_t hi, lo;
                            split2(g0 * hv[nt][half].x, g1 * hv[nt][half].y, hi, lo);
                            store_pk(g_rhpk4, b, j >> 1, hi, lo);
                        }
                    }
            }
        }
        grid_barrier();

        // ---------- phase B: s gate + h update ----------
        {
            const float* __restrict__ xs = g_xbuf + ((size_t)t * 3 + 2) * kB * kDh;
            const float* __restrict__ hp = g_hs + (size_t)t * kB * kDh;
            float* __restrict__ hn       = g_hs + (size_t)(t + 1) * kB * kDh;

            float2 xv[2][2], hv[2][2], zv[2][2];
            if (kh == 0) {
#pragma unroll
                for (int nt = 0; nt < 2; nt++)
#pragma unroll
                    for (int half = 0; half < 2; half++) {
                        const int b = wm + grp + half * 8;
                        const int j = jB + nt * 8 + 2 * tg;
                        const size_t o = (size_t)b * kDh + j;
                        xv[nt][half] = *reinterpret_cast<const float2*>(xs + o);
                        hv[nt][half] = *reinterpret_cast<const float2*>(hp + o);
                        zv[nt][half] = *reinterpret_cast<const float2*>(g_z + o);
                    }
            }

            float acc[2][4];
            gemm_smem<2, CPB>(g_rhpk4, smemB, ks0, wm, grp, tg, acc);

            if (kh == 1) {
#pragma unroll
                for (int nt = 0; nt < 2; nt++)
#pragma unroll
                    for (int i = 0; i < 4; i++)
                        red[(mq * 16 + nt * 4 + i) * 32 + lane] = acc[nt][i];
            }
            __syncthreads();
            if (kh == 0) {
#pragma unroll
                for (int nt = 0; nt < 2; nt++)
#pragma unroll
                    for (int i = 0; i < 4; i++)
                        acc[nt][i] += red[(mq * 16 + nt * 4 + i) * 32 + lane];
#pragma unroll
                for (int nt = 0; nt < 2; nt++)
#pragma unroll
                    for (int half = 0; half < 2; half++) {
                        const int b = wm + grp + half * 8;
                        const int j = jB + nt * 8 + 2 * tg;
                        const size_t o = (size_t)b * kDh + j;
                        const float st0 = tanhf(acc[nt][2 * half + 0] + xv[nt][half].x);
                        const float st1 = tanhf(acc[nt][2 * half + 1] + xv[nt][half].y);
                        const float h0 = hv[nt][half].x, h1 = hv[nt][half].y;
                        const float v0 = fmaf(zv[nt][half].x, st0 - h0, h0);
                        const float v1 = fmaf(zv[nt][half].y, st1 - h1, h1);
                        *reinterpret_cast<float2*>(hn + o) = make_float2(v0, v1);
                        uint32_t hi, lo;
                        split2(v0, v1, hi, lo);
                        store_pk(g_hpk4, b, j >> 1, hi, lo);
                        g_hspk[((size_t)t * kB + b) * kKP + (j >> 1)] = make_uint2(hi, lo);
                    }
            }
        }
        grid_barrier();
    }
}

// ---------------- output projection: relu(hs @ Wo + bo), packed operands -----

__global__ void out_proj_kernel(const float* __restrict__ bo,
                                float* __restrict__ out) {
    const int t  = blockIdx.x;
    const int c0 = blockIdx.y * 64;

    __shared__ uint32_t Ah[64][17], Al[64][17];
    __shared__ uint32_t Bh[64][17], Bl[64][17];

    const int tid = threadIdx.x;
    const int wid = tid >> 5, lane = tid & 31;
    const int wm  = (wid & 3) * 16;
    const int wn  = (wid >> 2) * 32;
    const int grp = lane >> 2, tg = lane & 3;

    const uint2* __restrict__ Apk = g_hspk + (size_t)t * kB * kKP;

    float acc[4][4] = {};

    for (int kp0 = 0; kp0 < kKP; kp0 += 16) {
        for (int idx = tid; idx < 64 * 16; idx += 256) {
            int kp = idx & 15, m = idx >> 4;
            uint2 v = Apk[(size_t)m * kKP + kp0 + kp];
            Ah[m][kp] = v.x; Al[m][kp] = v.y;
        }
        for (int idx = tid; idx < 64 * 16; idx += 256) {
            int kp = idx & 15, j = idx >> 4;
            uint2 v = g_wopk[(size_t)(c0 + j) * kKP + kp0 + kp];
            Bh[j][kp] = v.x; Bl[j][kp] = v.y;
        }
        __syncthreads();
#pragma unroll
        for (int kt = 0; kt < 2; kt++) {
            uint32_t ah[4], al[4];
            ah[0] = Ah[wm + grp][kt * 8 + tg];         al[0] = Al[wm + grp][kt * 8 + tg];
            ah[1] = Ah[wm + grp + 8][kt * 8 + tg];     al[1] = Al[wm + grp + 8][kt * 8 + tg];
            ah[2] = Ah[wm + grp][kt * 8 + tg + 4];     al[2] = Al[wm + grp][kt * 8 + tg + 4];
            ah[3] = Ah[wm + grp + 8][kt * 8 + tg + 4]; al[3] = Al[wm + grp + 8][kt * 8 + tg + 4];
#pragma unroll
            for (int nt = 0; nt < 4; nt++) {
                const int jj = wn + nt * 8 + grp;
                uint32_t bh[2], bl[2];
                bh[0] = Bh[jj][kt * 8 + tg];     bl[0] = Bl[jj][kt * 8 + tg];
                bh[1] = Bh[jj][kt * 8 + tg + 4]; bl[1] = Bl[jj][kt * 8 + tg + 4];
                mma16(acc[nt], ah, bh);
                mma16(acc[nt], ah, bl);
                mma16(acc[nt], al, bh);
            }
        }
        __syncthreads();
    }

#pragma unroll
    for (int nt = 0; nt < 4; nt++) {
#pragma unroll
        for (int cc = 0; cc < 4; cc++) {
            int b   = wm + grp + ((cc & 2) ? 8 : 0);
            int col = c0 + wn + nt * 8 + 2 * tg + (cc & 1);
            float v = acc[nt][cc] + bo[col];
            out[((size_t)b * kT + t) * kDout + col] = fmaxf(v, 0.0f);
        }
    }
}

// ---------------- h_final copy ----------------------------------------------

__global__ void final_copy_kernel(float* __restrict__ out) {
    int i = blockIdx.x * blockDim.x + threadIdx.x;
    if (i < kB * kDh)
        out[(size_t)kB * kT * kDout + i] = g_hs[(size_t)kT * kB * kDh + i];
}

// ---------------- launch ------------------------------------------------------
// d_in: inputs, Wz, bz, Wr, br, Ws, bs, Wo, bo ; d_out: [outputs | h_final] fp32

extern "C" void kernel_launch(void* const* d_in, const int* in_sizes, int n_in,
                              void* d_out, int out_size) {
    (void)in_sizes; (void)n_in; (void)out_size;
    const float* inp = (const float*)d_in[0];
    const float* Wz  = (const float*)d_in[1];
    const float* bz  = (const float*)d_in[2];
    const float* Wr  = (const float*)d_in[3];
    const float* br  = (const float*)d_in[4];
    const float* Ws  = (const float*)d_in[5];
    const float* bs  = (const float*)d_in[6];
    const float* Wo  = (const float*)d_in[7];
    const float* bo  = (const float*)d_in[8];
    float* out = (float*)d_out;

    cudaFuncSetAttribute(recur_kernel, cudaFuncAttributeMaxDynamicSharedMemorySize,
                         (int)kSmemBytes);

    zero_h0_kernel<<<(kB * kDh + 255) / 256, 256>>>();
    prep_w_kernel<<<(3 * kKP * kDh + 255) / 256, 256>>>(Wz, Wr, Ws);
    prep_wx_kernel<<<(3 * kDh * kKPx + 255) / 256, 256>>>(Wz, Wr, Ws);
    prep_wo_kernel<<<(kDout * kKP + 255) / 256, 256>>>(Wo);
    prep_in_kernel<<<(kB * kT * kKPx + 255) / 256, 256>>>(inp);
    proj_x_kernel<<<dim3(kB * kT / 64, 3 * kDh / 64), 256>>>(bz, br, bs);
    recur_kernel<<<kNC, 256, kSmemBytes>>>();
    out_proj_kernel<<<dim3(kT, kDout / 64), 256>>>(bo, out);
    final_copy_kernel<<<(kB * kDh + 255) / 256, 256>>>(out);
}

// round 11
// speedup vs baseline: 2.1475x; 1.1063x over previous
#include <cuda_runtime.h>
#include <cuda_bf16.h>
#include <cstdint>
#include <cstddef>

#define DEV_INLINE __device__ __forceinline__

namespace {
constexpr int kB    = 64;
constexpr int kT    = 512;
constexpr int kDin  = 512;
constexpr int kDh   = 1024;
constexpr int kDout = 1024;
constexpr int kNC   = 128;       // persistent CTA count (<=148 SMs, co-resident)
constexpr int kKP   = kDh / 2;   // 512 k-pairs (recurrent K)
constexpr int kKPx  = kDin / 2;  // 256 k-pairs (input K)
constexpr int kKS   = kKP / 8;   // 64 k-chunks (16 elems each)
constexpr int CPA   = 17;        // padded col stride, phase A smem B (16 cols)
constexpr int CPB   = 9;         // padded col stride, phase B smem B (8 cols)
constexpr int kSmemA4 = kKS * 4 * CPA;              // uint4 count
constexpr int kSmemB4 = kKS * 4 * CPB;
constexpr int kRedFloats = 64 * 32;                 // reduction buffer
constexpr size_t kSmemBytes = (size_t)(kSmemA4 + kSmemB4) * 16 + kRedFloats * 4; // ~114KB
}

// ---------------- device scratch (no allocs allowed) ------------------------
__device__ float g_xbuf[(size_t)kT * 3 * kB * kDh];   // [t][gate][b][j], x-proj + bias
__device__ float g_hs[(size_t)(kT + 1) * kB * kDh];   // [t][b][j]
__device__ float g_z[(size_t)kB * kDh];               // z gate (per step)
// packed GEMM-A operands, uint4 = { pk(8ks+q).hi, .lo, pk(8ks+q+4).hi, .lo }
__device__ uint4 g_hpk4[(size_t)kB * kKS * 4];        // current h packed
__device__ uint4 g_rhpk4[(size_t)kB * kKS * 4];       // r*h packed
__device__ uint2 g_wpk[(size_t)3 * kDh * kKP];        // W*_h packed, [gate][j][kp]
// pre-packed operands for the parallel GEMMs
__device__ uint2 g_inpk[(size_t)kB * kT * kKPx];      // inputs packed [row=b*T+t][kp]
__device__ uint2 g_wxpk[(size_t)3 * kDh * kKPx];      // W*_x packed [gate][j][kp]
__device__ uint2 g_wopk[(size_t)kDout * kKP];         // Wo packed [o][kp]
__device__ uint2 g_hspk[(size_t)kT * kB * kKP];       // h history packed [t][b][kp]
__device__ unsigned g_bar_cnt = 0;
__device__ unsigned g_bar_gen = 0;

// ---------------- bf16 split helpers ----------------------------------------

DEV_INLINE void split2(float x0, float x1, uint32_t& hi, uint32_t& lo) {
    __nv_bfloat16 h0 = __float2bfloat16_rn(x0);
    __nv_bfloat16 h1 = __float2bfloat16_rn(x1);
    __nv_bfloat16 l0 = __float2bfloat16_rn(x0 - __bfloat162float(h0));
    __nv_bfloat16 l1 = __float2bfloat16_rn(x1 - __bfloat162float(h1));
    hi = (uint32_t)__bfloat16_as_ushort(h0) | ((uint32_t)__bfloat16_as_ushort(h1) << 16);
    lo = (uint32_t)__bfloat16_as_ushort(l0) | ((uint32_t)__bfloat16_as_ushort(l1) << 16);
}

// D += A(16x16, row) * B(16x8, col), bf16 in, fp32 accum
DEV_INLINE void mma16(float c[4], const uint32_t a[4], const uint32_t b[2]) {
    asm volatile(
        "mma.sync.aligned.m16n8k16.row.col.f32.bf16.bf16.f32 "
        "{%0,%1,%2,%3}, {%4,%5,%6,%7}, {%8,%9}, {%0,%1,%2,%3};\n"
        : "+f"(c[0]), "+f"(c[1]), "+f"(c[2]), "+f"(c[3])
        : "r"(a[0]), "r"(a[1]), "r"(a[2]), "r"(a[3]), "r"(b[0]), "r"(b[1]));
}

DEV_INLINE float sigmoidf_(float x) { return 1.0f / (1.0f + __expf(-x)); }

// ---------------- init -------------------------------------------------------

__global__ void zero_h0_kernel() {
    int i = blockIdx.x * blockDim.x + threadIdx.x;
    if (i < kB * kDh) g_hs[i] = 0.0f;
    if (i < kB * kKS * 4) g_hpk4[i] = make_uint4(0u, 0u, 0u, 0u);
}

// ---------------- packers ----------------------------------------------------

__global__ void prep_w_kernel(const float* __restrict__ Wz,
                              const float* __restrict__ Wr,
                              const float* __restrict__ Ws) {
    size_t i = (size_t)blockIdx.x * blockDim.x + threadIdx.x;
    if (i >= (size_t)3 * kKP * kDh) return;
    int j  = (int)(i & (kDh - 1));
    int kp = (int)((i >> 10) & (kKP - 1));
    int g  = (int)(i >> 19);
    const float* W = (g == 0) ? Wz : (g == 1) ? Wr : Ws;
    uint32_t hi, lo;
    split2(W[(size_t)(2 * kp) * kDh + j], W[(size_t)(2 * kp + 1) * kDh + j], hi, lo);
    g_wpk[((size_t)g * kDh + j) * kKP + kp] = make_uint2(hi, lo);
}

__global__ void prep_wx_kernel(const float* __restrict__ Wz,
                               const float* __restrict__ Wr,
                               const float* __restrict__ Ws) {
    size_t i = (size_t)blockIdx.x * blockDim.x + threadIdx.x;
    if (i >= (size_t)3 * kDh * kKPx) return;
    int kp = (int)(i & (kKPx - 1));
    int j  = (int)((i >> 8) & (kDh - 1));
    int g  = (int)(i >> 18);
    const float* W = (g == 0) ? Wz : (g == 1) ? Wr : Ws;
    uint32_t hi, lo;
    split2(W[(size_t)(kDh + 2 * kp) * kDh + j],
           W[(size_t)(kDh + 2 * kp + 1) * kDh + j], hi, lo);
    g_wxpk[((size_t)g * kDh + j) * kKPx + kp] = make_uint2(hi, lo);
}

__global__ void prep_wo_kernel(const float* __restrict__ Wo) {
    size_t i = (size_t)blockIdx.x * blockDim.x + threadIdx.x;
    if (i >= (size_t)kDout * kKP) return;
    int kp = (int)(i & (kKP - 1));
    int o  = (int)(i >> 9);
    uint32_t hi, lo;
    split2(Wo[(size_t)(2 * kp) * kDout + o], Wo[(size_t)(2 * kp + 1) * kDout + o], hi, lo);
    g_wopk[(size_t)o * kKP + kp] = make_uint2(hi, lo);
}

__global__ void prep_in_kernel(const float* __restrict__ inp) {
    size_t i = (size_t)blockIdx.x * blockDim.x + threadIdx.x;
    if (i >= (size_t)kB * kT * kKPx) return;
    const float2 v = *reinterpret_cast<const float2*>(inp + 2 * i);
    uint32_t hi, lo;
    split2(v.x, v.y, hi, lo);
    g_inpk[i] = make_uint2(hi, lo);
}

// ---------------- x-projections (packed operands, pure GEMM) -----------------

__global__ void proj_x_kernel(const float* __restrict__ bz,
                              const float* __restrict__ br,
                              const float* __restrict__ bs) {
    const int r0   = blockIdx.x * 64;
    const int c0   = blockIdx.y * 64;
    const int gate = c0 >> 10;
    const int jg0  = c0 & (kDh - 1);
    const float* __restrict__ bias = (gate == 0) ? bz : (gate == 1) ? br : bs;

    __shared__ uint32_t Ah[64][17], Al[64][17];
    __shared__ uint32_t Bh[64][17], Bl[64][17];

    const int tid = threadIdx.x;
    const int wid = tid >> 5, lane = tid & 31;
    const int wm  = (wid & 3) * 16;
    const int wn  = (wid >> 2) * 32;
    const int grp = lane >> 2, tg = lane & 3;

    const uint2* __restrict__ Bw = g_wxpk + (size_t)gate * kDh * kKPx;

    float acc[4][4] = {};

    for (int kp0 = 0; kp0 < kKPx; kp0 += 16) {
        for (int idx = tid; idx < 64 * 16; idx += 256) {
            int kp = idx & 15, m = idx >> 4;
            uint2 v = g_inpk[(size_t)(r0 + m) * kKPx + kp0 + kp];
            Ah[m][kp] = v.x; Al[m][kp] = v.y;
        }
        for (int idx = tid; idx < 64 * 16; idx += 256) {
            int kp = idx & 15, j = idx >> 4;
            uint2 v = Bw[(size_t)(jg0 + j) * kKPx + kp0 + kp];
            Bh[j][kp] = v.x; Bl[j][kp] = v.y;
        }
        __syncthreads();
#pragma unroll
        for (int kt = 0; kt < 2; kt++) {
            uint32_t ah[4], al[4];
            ah[0] = Ah[wm + grp][kt * 8 + tg];         al[0] = Al[wm + grp][kt * 8 + tg];
            ah[1] = Ah[wm + grp + 8][kt * 8 + tg];     al[1] = Al[wm + grp + 8][kt * 8 + tg];
            ah[2] = Ah[wm + grp][kt * 8 + tg + 4];     al[2] = Al[wm + grp][kt * 8 + tg + 4];
            ah[3] = Ah[wm + grp + 8][kt * 8 + tg + 4]; al[3] = Al[wm + grp + 8][kt * 8 + tg + 4];
#pragma unroll
            for (int nt = 0; nt < 4; nt++) {
                const int jj = wn + nt * 8 + grp;
                uint32_t bh[2], bl[2];
                bh[0] = Bh[jj][kt * 8 + tg];     bl[0] = Bl[jj][kt * 8 + tg];
                bh[1] = Bh[jj][kt * 8 + tg + 4]; bl[1] = Bl[jj][kt * 8 + tg + 4];
                mma16(acc[nt], ah, bh);
                mma16(acc[nt], ah, bl);
                mma16(acc[nt], al, bh);
            }
        }
        __syncthreads();
    }

#pragma unroll
    for (int nt = 0; nt < 4; nt++) {
#pragma unroll
        for (int cc = 0; cc < 4; cc++) {
            int row = r0 + wm + grp + ((cc & 2) ? 8 : 0);
            int col = jg0 + wn + nt * 8 + 2 * tg + (cc & 1);
            int b = row >> 9;
            int t = row & (kT - 1);
            g_xbuf[(((size_t)t * 3 + gate) * kB + b) * kDh + col] = acc[nt][cc] + bias[col];
        }
    }
}

// ---------------- fast grid barrier (acquire/release) ------------------------

DEV_INLINE void grid_barrier() {
    __syncthreads();
    if (threadIdx.x == 0) {
        unsigned gen;
        asm volatile("ld.acquire.gpu.global.u32 %0, [%1];"
                     : "=r"(gen) : "l"(&g_bar_gen));
        unsigned old;
        asm volatile("atom.release.gpu.global.add.u32 %0, [%1], 1;"
                     : "=r"(old) : "l"(&g_bar_cnt));
        if (old == kNC - 1u) {
            asm volatile("st.relaxed.gpu.global.u32 [%0], 0;" :: "l"(&g_bar_cnt));
            asm volatile("st.release.gpu.global.u32 [%0], %1;"
                         :: "l"(&g_bar_gen), "r"(gen + 1u));
        } else {
            unsigned cur;
            do {
                asm volatile("ld.acquire.gpu.global.u32 %0, [%1];"
                             : "=r"(cur) : "l"(&g_bar_gen));
            } while (cur == gen);
        }
    }
    __syncthreads();
}

// ---------------- GEMM core: warp m16 x (NT*8), 32 k-chunks, B from smem -----

template <int NT, int CPAD>
DEV_INLINE void gemm_smem(const uint4* __restrict__ A4, const uint4* __restrict__ Bs,
                          int ks0, int wm, int grp, int tg, float out[NT][4]) {
    const uint4* __restrict__ r0p = A4 + (size_t)(wm + grp) * (kKS * 4) + tg;
    const uint4* __restrict__ r1p = A4 + (size_t)(wm + grp + 8) * (kKS * 4) + tg;

    float hh[NT][4], hl[NT][4], lh[NT][4];
#pragma unroll
    for (int nt = 0; nt < NT; nt++)
#pragma unroll
        for (int i = 0; i < 4; i++) { hh[nt][i] = 0.f; hl[nt][i] = 0.f; lh[nt][i] = 0.f; }

    uint4 abuf[2][2];
    abuf[0][0] = r0p[ks0 * 4];        abuf[0][1] = r1p[ks0 * 4];
    abuf[1][0] = r0p[(ks0 + 1) * 4];  abuf[1][1] = r1p[(ks0 + 1) * 4];

#pragma unroll 4
    for (int s = 0; s < 32; s++) {
        const int ks = ks0 + s;
        const uint4 a0 = abuf[s & 1][0];
        const uint4 a1 = abuf[s & 1][1];
        if (s + 2 < 32) {
            abuf[s & 1][0] = r0p[(ks + 2) * 4];
            abuf[s & 1][1] = r1p[(ks + 2) * 4];
        }
        uint4 bq[NT];
        const uint4* __restrict__ brow = Bs + (ks * 4 + tg) * CPAD + grp;
#pragma unroll
        for (int nt = 0; nt < NT; nt++) bq[nt] = brow[nt * 8];

        const uint32_t ah[4] = {a0.x, a1.x, a0.z, a1.z};
        const uint32_t al[4] = {a0.y, a1.y, a0.w, a1.w};
#pragma unroll
        for (int nt = 0; nt < NT; nt++) {
            const uint32_t bh[2] = {bq[nt].x, bq[nt].z};
            const uint32_t bl[2] = {bq[nt].y, bq[nt].w};
            mma16(hh[nt], ah, bh);
            mma16(hl[nt], ah, bl);
            mma16(lh[nt], al, bh);
        }
    }
#pragma unroll
    for (int nt = 0; nt < NT; nt++)
#pragma unroll
        for (int i = 0; i < 4; i++) out[nt][i] = hh[nt][i] + hl[nt][i] + lh[nt][i];
}

// write packed pair (uint2) for k-pair kp of row b into a [row][ks][q] uint4 array
DEV_INLINE void store_pk(uint4* arr, int b, int kp, uint32_t hi, uint32_t lo) {
    int ks = kp >> 3, q = kp & 3, half = (kp >> 2) & 1;
    uint2* p = reinterpret_cast<uint2*>(arr + ((size_t)b * kKS + ks) * 4 + q) + half;
    *p = make_uint2(hi, lo);
}

// ---------------- persistent recurrence kernel -------------------------------
// 128 CTAs x 256 threads. Warp = (mq = wid&3 -> 16-row block, kh = wid>>2 -> K half).
// Phase A: CTAs 0..63 -> z cols 16c..16c+15; CTAs 64..127 -> r cols (NT=2).
// Phase B: CTA c -> s cols 8c..8c+7 (NT=1). Cross-K reduction in smem.

__global__ void __launch_bounds__(256, 1) recur_kernel() {
    extern __shared__ uint4 smem[];
    uint4* smemA = smem;                       // 16 cols, stride CPA
    uint4* smemB = smem + kSmemA4;             // 8 cols, stride CPB
    float* red   = reinterpret_cast<float*>(smem + kSmemA4 + kSmemB4);

    const int c    = blockIdx.x;
    const int tid  = threadIdx.x;
    const int wid  = tid >> 5, lane = tid & 31;
    const int mq   = wid & 3, kh = wid >> 2;
    const int wm   = mq * 16;
    const int ks0  = kh * 32;
    const int grp  = lane >> 2, tg = lane & 3;

    const int gate = (c >= 64) ? 1 : 0;
    const int jA   = (c & 63) * 16;
    const int jB   = c * 8;

    // ---- prolog: load this CTA's weight slices into smem (once) ----
    {
        const uint2* __restrict__ wa = g_wpk + ((size_t)gate * kDh + jA) * kKP;
        for (int idx = tid; idx < 16 * kKP; idx += 256) {
            int j = idx >> 9, kp = idx & (kKP - 1);
            uint2 v = wa[(size_t)j * kKP + kp];
            int ks = kp >> 3, q = kp & 3, half = (kp >> 2) & 1;
            uint2* p = reinterpret_cast<uint2*>(&smemA[(ks * 4 + q) * CPA + j]) + half;
            *p = v;
        }
        const uint2* __restrict__ wb = g_wpk + ((size_t)2 * kDh + jB) * kKP;
        for (int idx = tid; idx < 8 * kKP; idx += 256) {
            int j = idx >> 9, kp = idx & (kKP - 1);
            uint2 v = wb[(size_t)j * kKP + kp];
            int ks = kp >> 3, q = kp & 3, half = (kp >> 2) & 1;
            uint2* p = reinterpret_cast<uint2*>(&smemB[(ks * 4 + q) * CPB + j]) + half;
            *p = v;
        }
        __syncthreads();
    }

    for (int t = 0; t < kT; ++t) {
        // ---------- phase A: z (CTAs 0..63) or r (CTAs 64..127) ----------
        {
            const float* __restrict__ xg = g_xbuf + ((size_t)t * 3 + gate) * kB * kDh;
            const float* __restrict__ hp = g_hs + (size_t)t * kB * kDh;

            float2 xv[2][2], hv[2][2];
            if (kh == 0) {
#pragma unroll
                for (int nt = 0; nt < 2; nt++)
#pragma unroll
                    for (int half = 0; half < 2; half++) {
                        const int b = wm + grp + half * 8;
                        const int j = jA + nt * 8 + 2 * tg;
                        xv[nt][half] = *reinterpret_cast<const float2*>(xg + (size_t)b * kDh + j);
                        if (gate)
                            hv[nt][half] = *reinterpret_cast<const float2*>(hp + (size_t)b * kDh + j);
                    }
            }

            float acc[2][4];
            gemm_smem<2, CPA>(g_hpk4, smemA, ks0, wm, grp, tg, acc);

            if (kh == 1) {
#pragma unroll
                for (int nt = 0; nt < 2; nt++)
#pragma unroll
                    for (int i = 0; i < 4; i++)
                        red[(mq * 16 + nt * 4 + i) * 32 + lane] = acc[nt][i];
            }
            __syncthreads();
            if (kh == 0) {
#pragma unroll
                for (int nt = 0; nt < 2; nt++)
#pragma unroll
                    for (int i = 0; i < 4; i++)
                        acc[nt][i] += red[(mq * 16 + nt * 4 + i) * 32 + lane];
#pragma unroll
                for (int nt = 0; nt < 2; nt++)
#pragma unroll
                    for (int half = 0; half < 2; half++) {
                        const int b = wm + grp + half * 8;
                        const int j = jA + nt * 8 + 2 * tg;
                        const float g0 = sigmoidf_(acc[nt][2 * half + 0] + xv[nt][half].x);
                        const float g1 = sigmoidf_(acc[nt][2 * half + 1] + xv[nt][half].y);
                        if (gate == 0) {
                            *reinterpret_cast<float2*>(g_z + (size_t)b * kDh + j) =
                                make_float2(g0, g1);
                        } else {
                            uint32_t hi, lo;
                            split2(g0 * hv[nt][half].x, g1 * hv[nt][half].y, hi, lo);
                            store_pk(g_rhpk4, b, j >> 1, hi, lo);
                        }
                    }
            }
        }
        grid_barrier();

        // ---------- phase B: s gate + h update ----------
        {
            const float* __restrict__ xs = g_xbuf + ((size_t)t * 3 + 2) * kB * kDh;
            const float* __restrict__ hp = g_hs + (size_t)t * kB * kDh;
            float* __restrict__ hn       = g_hs + (size_t)(t + 1) * kB * kDh;

            float2 xv[2], hv[2], zv[2];
            if (kh == 0) {
#pragma unroll
                for (int half = 0; half < 2; half++) {
                    const int b = wm + grp + half * 8;
                    const int j = jB + 2 * tg;
                    const size_t o = (size_t)b * kDh + j;
                    xv[half] = *reinterpret_cast<const float2*>(xs + o);
                    hv[half] = *reinterpret_cast<const float2*>(hp + o);
                    zv[half] = *reinterpret_cast<const float2*>(g_z + o);
                }
            }

            float acc[1][4];
            gemm_smem<1, CPB>(g_rhpk4, smemB, ks0, wm, grp, tg, acc);

            if (kh == 1) {
#pragma unroll
                for (int i = 0; i < 4; i++)
                    red[(mq * 16 + i) * 32 + lane] = acc[0][i];
            }
            __syncthreads();
            if (kh == 0) {
#pragma unroll
                for (int i = 0; i < 4; i++)
                    acc[0][i] += red[(mq * 16 + i) * 32 + lane];
#pragma unroll
                for (int half = 0; half < 2; half++) {
                    const int b = wm + grp + half * 8;
                    const int j = jB + 2 * tg;
                    const size_t o = (size_t)b * kDh + j;
                    const float st0 = tanhf(acc[0][2 * half + 0] + xv[half].x);
                    const float st1 = tanhf(acc[0][2 * half + 1] + xv[half].y);
                    const float h0 = hv[half].x, h1 = hv[half].y;
                    const float v0 = fmaf(zv[half].x, st0 - h0, h0);
                    const float v1 = fmaf(zv[half].y, st1 - h1, h1);
                    *reinterpret_cast<float2*>(hn + o) = make_float2(v0, v1);
                    uint32_t hi, lo;
                    split2(v0, v1, hi, lo);
                    store_pk(g_hpk4, b, j >> 1, hi, lo);
                    g_hspk[((size_t)t * kB + b) * kKP + (j >> 1)] = make_uint2(hi, lo);
                }
            }
        }
        grid_barrier();
    }
}

// ---------------- output projection: relu(hs @ Wo + bo), packed operands -----

__global__ void out_proj_kernel(const float* __restrict__ bo,
                                float* __restrict__ out) {
    const int t  = blockIdx.x;
    const int c0 = blockIdx.y * 64;

    __shared__ uint32_t Ah[64][17], Al[64][17];
    __shared__ uint32_t Bh[64][17], Bl[64][17];

    const int tid = threadIdx.x;
    const int wid = tid >> 5, lane = tid & 31;
    const int wm  = (wid & 3) * 16;
    const int wn  = (wid >> 2) * 32;
    const int grp = lane >> 2, tg = lane & 3;

    const uint2* __restrict__ Apk = g_hspk + (size_t)t * kB * kKP;

    float acc[4][4] = {};

    for (int kp0 = 0; kp0 < kKP; kp0 += 16) {
        for (int idx = tid; idx < 64 * 16; idx += 256) {
            int kp = idx & 15, m = idx >> 4;
            uint2 v = Apk[(size_t)m * kKP + kp0 + kp];
            Ah[m][kp] = v.x; Al[m][kp] = v.y;
        }
        for (int idx = tid; idx < 64 * 16; idx += 256) {
            int kp = idx & 15, j = idx >> 4;
            uint2 v = g_wopk[(size_t)(c0 + j) * kKP + kp0 + kp];
            Bh[j][kp] = v.x; Bl[j][kp] = v.y;
        }
        __syncthreads();
#pragma unroll
        for (int kt = 0; kt < 2; kt++) {
            uint32_t ah[4], al[4];
            ah[0] = Ah[wm + grp][kt * 8 + tg];         al[0] = Al[wm + grp][kt * 8 + tg];
            ah[1] = Ah[wm + grp + 8][kt * 8 + tg];     al[1] = Al[wm + grp + 8][kt * 8 + tg];
            ah[2] = Ah[wm + grp][kt * 8 + tg + 4];     al[2] = Al[wm + grp][kt * 8 + tg + 4];
            ah[3] = Ah[wm + grp + 8][kt * 8 + tg + 4]; al[3] = Al[wm + grp + 8][kt * 8 + tg + 4];
#pragma unroll
            for (int nt = 0; nt < 4; nt++) {
                const int jj = wn + nt * 8 + grp;
                uint32_t bh[2], bl[2];
                bh[0] = Bh[jj][kt * 8 + tg];     bl[0] = Bl[jj][kt * 8 + tg];
                bh[1] = Bh[jj][kt * 8 + tg + 4]; bl[1] = Bl[jj][kt * 8 + tg + 4];
                mma16(acc[nt], ah, bh);
                mma16(acc[nt], ah, bl);
                mma16(acc[nt], al, bh);
            }
        }
        __syncthreads();
    }

#pragma unroll
    for (int nt = 0; nt < 4; nt++) {
#pragma unroll
        for (int cc = 0; cc < 4; cc++) {
            int b   = wm + grp + ((cc & 2) ? 8 : 0);
            int col = c0 + wn + nt * 8 + 2 * tg + (cc & 1);
            float v = acc[nt][cc] + bo[col];
            out[((size_t)b * kT + t) * kDout + col] = fmaxf(v, 0.0f);
        }
    }
}

// ---------------- h_final copy ----------------------------------------------

__global__ void final_copy_kernel(float* __restrict__ out) {
    int i = blockIdx.x * blockDim.x + threadIdx.x;
    if (i < kB * kDh)
        out[(size_t)kB * kT * kDout + i] = g_hs[(size_t)kT * kB * kDh + i];
}

// ---------------- launch ------------------------------------------------------
// d_in: inputs, Wz, bz, Wr, br, Ws, bs, Wo, bo ; d_out: [outputs | h_final] fp32

extern "C" void kernel_launch(void* const* d_in, const int* in_sizes, int n_in,
                              void* d_out, int out_size) {
    (void)in_sizes; (void)n_in; (void)out_size;
    const float* inp = (const float*)d_in[0];
    const float* Wz  = (const float*)d_in[1];
    const float* bz  = (const float*)d_in[2];
    const float* Wr  = (const float*)d_in[3];
    const float* br  = (const float*)d_in[4];
    const float* Ws  = (const float*)d_in[5];
    const float* bs  = (const float*)d_in[6];
    const float* Wo  = (const float*)d_in[7];
    const float* bo  = (const float*)d_in[8];
    float* out = (float*)d_out;

    cudaFuncSetAttribute(recur_kernel, cudaFuncAttributeMaxDynamicSharedMemorySize,
                         (int)kSmemBytes);

    zero_h0_kernel<<<(kB * kDh + 255) / 256, 256>>>();
    prep_w_kernel<<<(3 * kKP * kDh + 255) / 256, 256>>>(Wz, Wr, Ws);
    prep_wx_kernel<<<(3 * kDh * kKPx + 255) / 256, 256>>>(Wz, Wr, Ws);
    prep_wo_kernel<<<(kDout * kKP + 255) / 256, 256>>>(Wo);
    prep_in_kernel<<<(kB * kT * kKPx + 255) / 256, 256>>>(inp);
    proj_x_kernel<<<dim3(kB * kT / 64, 3 * kDh / 64), 256>>>(bz, br, bs);
    recur_kernel<<<kNC, 256, kSmemBytes>>>();
    out_proj_kernel<<<dim3(kT, kDout / 64), 256>>>(bo, out);
    final_copy_kernel<<<(kB * kDh + 255) / 256, 256>>>(out);
}

// round 12
// speedup vs baseline: 2.3729x; 1.1049x over previous
#include <cuda_runtime.h>
#include <cuda_bf16.h>
#include <cstdint>
#include <cstddef>

#define DEV_INLINE __device__ __forceinline__

namespace {
constexpr int kB    = 64;
constexpr int kT    = 512;
constexpr int kDin  = 512;
constexpr int kDh   = 1024;
constexpr int kDout = 1024;
constexpr int kNC   = 128;       // persistent CTA count (<=148 SMs, co-resident)
constexpr int kKP   = kDh / 2;   // 512 k-pairs (recurrent K)
constexpr int kKPx  = kDin / 2;  // 256 k-pairs (input K)
constexpr int kKS   = kKP / 8;   // 64 k-chunks (16 elems each)
constexpr int CPA   = 17;        // padded col stride, phase A smem B (16 cols)
constexpr int CPB   = 9;         // padded col stride, phase B smem B (8 cols)
constexpr int kSmemA4 = kKS * 4 * CPA;              // uint4 count
constexpr int kSmemB4 = kKS * 4 * CPB;
constexpr int kRedFloats = 3 * 64 * 32;             // 3 partial layers x 64 "rows" x 32 lanes
constexpr size_t kSmemBytes = (size_t)(kSmemA4 + kSmemB4) * 16 + kRedFloats * 4;
}

// ---------------- device scratch (no allocs allowed) ------------------------
__device__ float g_xbuf[(size_t)kT * 3 * kB * kDh];   // [t][gate][b][j], x-proj + bias
__device__ float g_hs[(size_t)(kT + 1) * kB * kDh];   // [t][b][j]
__device__ float g_z[(size_t)kB * kDh];               // z gate (per step)
// packed GEMM-A operands, uint4 = { pk(8ks+q).hi, .lo, pk(8ks+q+4).hi, .lo }
__device__ uint4 g_hpk4[(size_t)kB * kKS * 4];        // current h packed
__device__ uint4 g_rhpk4[(size_t)kB * kKS * 4];       // r*h packed
__device__ uint2 g_wpk[(size_t)3 * kDh * kKP];        // W*_h packed, [gate][j][kp]
// pre-packed operands for the parallel GEMMs
__device__ uint2 g_inpk[(size_t)kB * kT * kKPx];      // inputs packed [row=b*T+t][kp]
__device__ uint2 g_wxpk[(size_t)3 * kDh * kKPx];      // W*_x packed [gate][j][kp]
__device__ uint2 g_wopk[(size_t)kDout * kKP];         // Wo packed [o][kp]
__device__ uint2 g_hspk[(size_t)kT * kB * kKP];       // h history packed [t][b][kp]
__device__ unsigned g_bar_cnt = 0;
__device__ unsigned g_bar_gen = 0;

// ---------------- bf16 split helpers ----------------------------------------

DEV_INLINE void split2(float x0, float x1, uint32_t& hi, uint32_t& lo) {
    __nv_bfloat16 h0 = __float2bfloat16_rn(x0);
    __nv_bfloat16 h1 = __float2bfloat16_rn(x1);
    __nv_bfloat16 l0 = __float2bfloat16_rn(x0 - __bfloat162float(h0));
    __nv_bfloat16 l1 = __float2bfloat16_rn(x1 - __bfloat162float(h1));
    hi = (uint32_t)__bfloat16_as_ushort(h0) | ((uint32_t)__bfloat16_as_ushort(h1) << 16);
    lo = (uint32_t)__bfloat16_as_ushort(l0) | ((uint32_t)__bfloat16_as_ushort(l1) << 16);
}

// D += A(16x16, row) * B(16x8, col), bf16 in, fp32 accum
DEV_INLINE void mma16(float c[4], const uint32_t a[4], const uint32_t b[2]) {
    asm volatile(
        "mma.sync.aligned.m16n8k16.row.col.f32.bf16.bf16.f32 "
        "{%0,%1,%2,%3}, {%4,%5,%6,%7}, {%8,%9}, {%0,%1,%2,%3};\n"
        : "+f"(c[0]), "+f"(c[1]), "+f"(c[2]), "+f"(c[3])
        : "r"(a[0]), "r"(a[1]), "r"(a[2]), "r"(a[3]), "r"(b[0]), "r"(b[1]));
}

DEV_INLINE float sigmoidf_(float x) { return 1.0f / (1.0f + __expf(-x)); }

// ---------------- init -------------------------------------------------------

__global__ void zero_h0_kernel() {
    int i = blockIdx.x * blockDim.x + threadIdx.x;
    if (i < kB * kDh) g_hs[i] = 0.0f;
    if (i < kB * kKS * 4) g_hpk4[i] = make_uint4(0u, 0u, 0u, 0u);
}

// ---------------- packers ----------------------------------------------------

__global__ void prep_w_kernel(const float* __restrict__ Wz,
                              const float* __restrict__ Wr,
                              const float* __restrict__ Ws) {
    size_t i = (size_t)blockIdx.x * blockDim.x + threadIdx.x;
    if (i >= (size_t)3 * kKP * kDh) return;
    int j  = (int)(i & (kDh - 1));
    int kp = (int)((i >> 10) & (kKP - 1));
    int g  = (int)(i >> 19);
    const float* W = (g == 0) ? Wz : (g == 1) ? Wr : Ws;
    uint32_t hi, lo;
    split2(W[(size_t)(2 * kp) * kDh + j], W[(size_t)(2 * kp + 1) * kDh + j], hi, lo);
    g_wpk[((size_t)g * kDh + j) * kKP + kp] = make_uint2(hi, lo);
}

__global__ void prep_wx_kernel(const float* __restrict__ Wz,
                               const float* __restrict__ Wr,
                               const float* __restrict__ Ws) {
    size_t i = (size_t)blockIdx.x * blockDim.x + threadIdx.x;
    if (i >= (size_t)3 * kDh * kKPx) return;
    int kp = (int)(i & (kKPx - 1));
    int j  = (int)((i >> 8) & (kDh - 1));
    int g  = (int)(i >> 18);
    const float* W = (g == 0) ? Wz : (g == 1) ? Wr : Ws;
    uint32_t hi, lo;
    split2(W[(size_t)(kDh + 2 * kp) * kDh + j],
           W[(size_t)(kDh + 2 * kp + 1) * kDh + j], hi, lo);
    g_wxpk[((size_t)g * kDh + j) * kKPx + kp] = make_uint2(hi, lo);
}

__global__ void prep_wo_kernel(const float* __restrict__ Wo) {
    size_t i = (size_t)blockIdx.x * blockDim.x + threadIdx.x;
    if (i >= (size_t)kDout * kKP) return;
    int kp = (int)(i & (kKP - 1));
    int o  = (int)(i >> 9);
    uint32_t hi, lo;
    split2(Wo[(size_t)(2 * kp) * kDout + o], Wo[(size_t)(2 * kp + 1) * kDout + o], hi, lo);
    g_wopk[(size_t)o * kKP + kp] = make_uint2(hi, lo);
}

__global__ void prep_in_kernel(const float* __restrict__ inp) {
    size_t i = (size_t)blockIdx.x * blockDim.x + threadIdx.x;
    if (i >= (size_t)kB * kT * kKPx) return;
    const float2 v = *reinterpret_cast<const float2*>(inp + 2 * i);
    uint32_t hi, lo;
    split2(v.x, v.y, hi, lo);
    g_inpk[i] = make_uint2(hi, lo);
}

// ---------------- x-projections (packed operands, pure GEMM) -----------------

__global__ void proj_x_kernel(const float* __restrict__ bz,
                              const float* __restrict__ br,
                              const float* __restrict__ bs) {
    const int r0   = blockIdx.x * 64;
    const int c0   = blockIdx.y * 64;
    const int gate = c0 >> 10;
    const int jg0  = c0 & (kDh - 1);
    const float* __restrict__ bias = (gate == 0) ? bz : (gate == 1) ? br : bs;

    __shared__ uint32_t Ah[64][17], Al[64][17];
    __shared__ uint32_t Bh[64][17], Bl[64][17];

    const int tid = threadIdx.x;
    const int wid = tid >> 5, lane = tid & 31;
    const int wm  = (wid & 3) * 16;
    const int wn  = (wid >> 2) * 32;
    const int grp = lane >> 2, tg = lane & 3;

    const uint2* __restrict__ Bw = g_wxpk + (size_t)gate * kDh * kKPx;

    float acc[4][4] = {};

    for (int kp0 = 0; kp0 < kKPx; kp0 += 16) {
        for (int idx = tid; idx < 64 * 16; idx += 256) {
            int kp = idx & 15, m = idx >> 4;
            uint2 v = g_inpk[(size_t)(r0 + m) * kKPx + kp0 + kp];
            Ah[m][kp] = v.x; Al[m][kp] = v.y;
        }
        for (int idx = tid; idx < 64 * 16; idx += 256) {
            int kp = idx & 15, j = idx >> 4;
            uint2 v = Bw[(size_t)(jg0 + j) * kKPx + kp0 + kp];
            Bh[j][kp] = v.x; Bl[j][kp] = v.y;
        }
        __syncthreads();
#pragma unroll
        for (int kt = 0; kt < 2; kt++) {
            uint32_t ah[4], al[4];
            ah[0] = Ah[wm + grp][kt * 8 + tg];         al[0] = Al[wm + grp][kt * 8 + tg];
            ah[1] = Ah[wm + grp + 8][kt * 8 + tg];     al[1] = Al[wm + grp + 8][kt * 8 + tg];
            ah[2] = Ah[wm + grp][kt * 8 + tg + 4];     al[2] = Al[wm + grp][kt * 8 + tg + 4];
            ah[3] = Ah[wm + grp + 8][kt * 8 + tg + 4]; al[3] = Al[wm + grp + 8][kt * 8 + tg + 4];
#pragma unroll
            for (int nt = 0; nt < 4; nt++) {
                const int jj = wn + nt * 8 + grp;
                uint32_t bh[2], bl[2];
                bh[0] = Bh[jj][kt * 8 + tg];     bl[0] = Bl[jj][kt * 8 + tg];
                bh[1] = Bh[jj][kt * 8 + tg + 4]; bl[1] = Bl[jj][kt * 8 + tg + 4];
                mma16(acc[nt], ah, bh);
                mma16(acc[nt], ah, bl);
                mma16(acc[nt], al, bh);
            }
        }
        __syncthreads();
    }

#pragma unroll
    for (int nt = 0; nt < 4; nt++) {
#pragma unroll
        for (int cc = 0; cc < 4; cc++) {
            int row = r0 + wm + grp + ((cc & 2) ? 8 : 0);
            int col = jg0 + wn + nt * 8 + 2 * tg + (cc & 1);
            int b = row >> 9;
            int t = row & (kT - 1);
            g_xbuf[(((size_t)t * 3 + gate) * kB + b) * kDh + col] = acc[nt][cc] + bias[col];
        }
    }
}

// ---------------- fast grid barrier (acquire/release) ------------------------

DEV_INLINE void grid_barrier() {
    __syncthreads();
    if (threadIdx.x == 0) {
        unsigned gen;
        asm volatile("ld.acquire.gpu.global.u32 %0, [%1];"
                     : "=r"(gen) : "l"(&g_bar_gen));
        unsigned old;
        asm volatile("atom.release.gpu.global.add.u32 %0, [%1], 1;"
                     : "=r"(old) : "l"(&g_bar_cnt));
        if (old == kNC - 1u) {
            asm volatile("st.relaxed.gpu.global.u32 [%0], 0;" :: "l"(&g_bar_cnt));
            asm volatile("st.release.gpu.global.u32 [%0], %1;"
                         :: "l"(&g_bar_gen), "r"(gen + 1u));
        } else {
            unsigned cur;
            do {
                asm volatile("ld.acquire.gpu.global.u32 %0, [%1];"
                             : "=r"(cur) : "l"(&g_bar_gen));
            } while (cur == gen);
        }
    }
    __syncthreads();
}

// ---------------- GEMM core: warp m16 x (NT*8), 16 k-chunks, B from smem -----

template <int NT, int CPAD>
DEV_INLINE void gemm_smem(const uint4* __restrict__ A4, const uint4* __restrict__ Bs,
                          int ks0, int wm, int grp, int tg, float out[NT][4]) {
    const uint4* __restrict__ r0p = A4 + (size_t)(wm + grp) * (kKS * 4) + tg;
    const uint4* __restrict__ r1p = A4 + (size_t)(wm + grp + 8) * (kKS * 4) + tg;

    float hh[NT][4], hl[NT][4], lh[NT][4];
#pragma unroll
    for (int nt = 0; nt < NT; nt++)
#pragma unroll
        for (int i = 0; i < 4; i++) { hh[nt][i] = 0.f; hl[nt][i] = 0.f; lh[nt][i] = 0.f; }

    uint4 abuf[2][2];
    abuf[0][0] = r0p[ks0 * 4];        abuf[0][1] = r1p[ks0 * 4];
    abuf[1][0] = r0p[(ks0 + 1) * 4];  abuf[1][1] = r1p[(ks0 + 1) * 4];

#pragma unroll 4
    for (int s = 0; s < 16; s++) {
        const int ks = ks0 + s;
        const uint4 a0 = abuf[s & 1][0];
        const uint4 a1 = abuf[s & 1][1];
        if (s + 2 < 16) {
            abuf[s & 1][0] = r0p[(ks + 2) * 4];
            abuf[s & 1][1] = r1p[(ks + 2) * 4];
        }
        uint4 bq[NT];
        const uint4* __restrict__ brow = Bs + (ks * 4 + tg) * CPAD + grp;
#pragma unroll
        for (int nt = 0; nt < NT; nt++) bq[nt] = brow[nt * 8];

        const uint32_t ah[4] = {a0.x, a1.x, a0.z, a1.z};
        const uint32_t al[4] = {a0.y, a1.y, a0.w, a1.w};
#pragma unroll
        for (int nt = 0; nt < NT; nt++) {
            const uint32_t bh[2] = {bq[nt].x, bq[nt].z};
            const uint32_t bl[2] = {bq[nt].y, bq[nt].w};
            mma16(hh[nt], ah, bh);
            mma16(hl[nt], ah, bl);
            mma16(lh[nt], al, bh);
        }
    }
#pragma unroll
    for (int nt = 0; nt < NT; nt++)
#pragma unroll
        for (int i = 0; i < 4; i++) out[nt][i] = hh[nt][i] + hl[nt][i] + lh[nt][i];
}

// write packed pair (uint2) for k-pair kp of row b into a [row][ks][q] uint4 array
DEV_INLINE void store_pk(uint4* arr, int b, int kp, uint32_t hi, uint32_t lo) {
    int ks = kp >> 3, q = kp & 3, half = (kp >> 2) & 1;
    uint2* p = reinterpret_cast<uint2*>(arr + ((size_t)b * kKS + ks) * 4 + q) + half;
    *p = make_uint2(hi, lo);
}

// ---------------- persistent recurrence kernel -------------------------------
// 128 CTAs x 512 threads. Warp = (mq = wid&3 -> 16-row block, kq = wid>>2 -> K quarter).
// Phase A: CTAs 0..63 -> z cols 16c..16c+15; CTAs 64..127 -> r cols (NT=2).
// Phase B: CTA c -> s cols 8c..8c+7 (NT=1). Cross-K reduction (4 partials) in smem.

__global__ void __launch_bounds__(512, 1) recur_kernel() {
    extern __shared__ uint4 smem[];
    uint4* smemA = smem;                       // 16 cols, stride CPA
    uint4* smemB = smem + kSmemA4;             // 8 cols, stride CPB
    float* red   = reinterpret_cast<float*>(smem + kSmemA4 + kSmemB4);

    const int c    = blockIdx.x;
    const int tid  = threadIdx.x;
    const int wid  = tid >> 5, lane = tid & 31;
    const int mq   = wid & 3, kq = wid >> 2;   // kq in 0..3
    const int wm   = mq * 16;
    const int ks0  = kq * 16;
    const int grp  = lane >> 2, tg = lane & 3;

    const int gate = (c >= 64) ? 1 : 0;
    const int jA   = (c & 63) * 16;
    const int jB   = c * 8;

    // ---- prolog: load this CTA's weight slices into smem (once) ----
    {
        const uint2* __restrict__ wa = g_wpk + ((size_t)gate * kDh + jA) * kKP;
        for (int idx = tid; idx < 16 * kKP; idx += 512) {
            int j = idx >> 9, kp = idx & (kKP - 1);
            uint2 v = wa[(size_t)j * kKP + kp];
            int ks = kp >> 3, q = kp & 3, half = (kp >> 2) & 1;
            uint2* p = reinterpret_cast<uint2*>(&smemA[(ks * 4 + q) * CPA + j]) + half;
            *p = v;
        }
        const uint2* __restrict__ wb = g_wpk + ((size_t)2 * kDh + jB) * kKP;
        for (int idx = tid; idx < 8 * kKP; idx += 512) {
            int j = idx >> 9, kp = idx & (kKP - 1);
            uint2 v = wb[(size_t)j * kKP + kp];
            int ks = kp >> 3, q = kp & 3, half = (kp >> 2) & 1;
            uint2* p = reinterpret_cast<uint2*>(&smemB[(ks * 4 + q) * CPB + j]) + half;
            *p = v;
        }
        __syncthreads();
    }

    for (int t = 0; t < kT; ++t) {
        // ---------- phase A: z (CTAs 0..63) or r (CTAs 64..127) ----------
        {
            const float* __restrict__ xg = g_xbuf + ((size_t)t * 3 + gate) * kB * kDh;
            const float* __restrict__ hp = g_hs + (size_t)t * kB * kDh;

            float2 xv[2][2], hv[2][2];
            if (kq == 0) {
#pragma unroll
                for (int nt = 0; nt < 2; nt++)
#pragma unroll
                    for (int half = 0; half < 2; half++) {
                        const int b = wm + grp + half * 8;
                        const int j = jA + nt * 8 + 2 * tg;
                        xv[nt][half] = *reinterpret_cast<const float2*>(xg + (size_t)b * kDh + j);
                        if (gate)
                            hv[nt][half] = *reinterpret_cast<const float2*>(hp + (size_t)b * kDh + j);
                    }
            }

            float acc[2][4];
            gemm_smem<2, CPA>(g_hpk4, smemA, ks0, wm, grp, tg, acc);

            if (kq > 0) {
#pragma unroll
                for (int nt = 0; nt < 2; nt++)
#pragma unroll
                    for (int i = 0; i < 4; i++)
                        red[((kq - 1) * 64 + mq * 16 + nt * 4 + i) * 32 + lane] = acc[nt][i];
            }
            __syncthreads();
            if (kq == 0) {
#pragma unroll
                for (int nt = 0; nt < 2; nt++)
#pragma unroll
                    for (int i = 0; i < 4; i++) {
                        const int r = (mq * 16 + nt * 4 + i) * 32 + lane;
                        acc[nt][i] += red[r] + red[64 * 32 + r] + red[2 * 64 * 32 + r];
                    }
#pragma unroll
                for (int nt = 0; nt < 2; nt++)
#pragma unroll
                    for (int half = 0; half < 2; half++) {
                        const int b = wm + grp + half * 8;
                        const int j = jA + nt * 8 + 2 * tg;
                        const float g0 = sigmoidf_(acc[nt][2 * half + 0] + xv[nt][half].x);
                        const float g1 = sigmoidf_(acc[nt][2 * half + 1] + xv[nt][half].y);
                        if (gate == 0) {
                            *reinterpret_cast<float2*>(g_z + (size_t)b * kDh + j) =
                                make_float2(g0, g1);
                        } else {
                            uint32_t hi, lo;
                            split2(g0 * hv[nt][half].x, g1 * hv[nt][half].y, hi, lo);
                            store_pk(g_rhpk4, b, j >> 1, hi, lo);
                        }
                    }
            }
        }
        grid_barrier();

        // ---------- phase B: s gate + h update ----------
        {
            const float* __restrict__ xs = g_xbuf + ((size_t)t * 3 + 2) * kB * kDh;
            const float* __restrict__ hp = g_hs + (size_t)t * kB * kDh;
            float* __restrict__ hn       = g_hs + (size_t)(t + 1) * kB * kDh;

            float2 xv[2], hv[2], zv[2];
            if (kq == 0) {
#pragma unroll
                for (int half = 0; half < 2; half++) {
                    const int b = wm + grp + half * 8;
                    const int j = jB + 2 * tg;
                    const size_t o = (size_t)b * kDh + j;
                    xv[half] = *reinterpret_cast<const float2*>(xs + o);
                    hv[half] = *reinterpret_cast<const float2*>(hp + o);
                    zv[half] = *reinterpret_cast<const float2*>(g_z + o);
                }
            }

            float acc[1][4];
            gemm_smem<1, CPB>(g_rhpk4, smemB, ks0, wm, grp, tg, acc);

            if (kq > 0) {
#pragma unroll
                for (int i = 0; i < 4; i++)
                    red[((kq - 1) * 64 + mq * 16 + i) * 32 + lane] = acc[0][i];
            }
            __syncthreads();
            if (kq == 0) {
#pragma unroll
                for (int i = 0; i < 4; i++) {
                    const int r = (mq * 16 + i) * 32 + lane;
                    acc[0][i] += red[r] + red[64 * 32 + r] + red[2 * 64 * 32 + r];
                }
#pragma unroll
                for (int half = 0; half < 2; half++) {
                    const int b = wm + grp + half * 8;
                    const int j = jB + 2 * tg;
                    const size_t o = (size_t)b * kDh + j;
                    const float st0 = tanhf(acc[0][2 * half + 0] + xv[half].x);
                    const float st1 = tanhf(acc[0][2 * half + 1] + xv[half].y);
                    const float h0 = hv[half].x, h1 = hv[half].y;
                    const float v0 = fmaf(zv[half].x, st0 - h0, h0);
                    const float v1 = fmaf(zv[half].y, st1 - h1, h1);
                    *reinterpret_cast<float2*>(hn + o) = make_float2(v0, v1);
                    uint32_t hi, lo;
                    split2(v0, v1, hi, lo);
                    store_pk(g_hpk4, b, j >> 1, hi, lo);
                    g_hspk[((size_t)t * kB + b) * kKP + (j >> 1)] = make_uint2(hi, lo);
                }
            }
        }
        grid_barrier();
    }
}

// ---------------- output projection: relu(hs @ Wo + bo), packed operands -----

__global__ void out_proj_kernel(const float* __restrict__ bo,
                                float* __restrict__ out) {
    const int t  = blockIdx.x;
    const int c0 = blockIdx.y * 64;

    __shared__ uint32_t Ah[64][17], Al[64][17];
    __shared__ uint32_t Bh[64][17], Bl[64][17];

    const int tid = threadIdx.x;
    const int wid = tid >> 5, lane = tid & 31;
    const int wm  = (wid & 3) * 16;
    const int wn  = (wid >> 2) * 32;
    const int grp = lane >> 2, tg = lane & 3;

    const uint2* __restrict__ Apk = g_hspk + (size_t)t * kB * kKP;

    float acc[4][4] = {};

    for (int kp0 = 0; kp0 < kKP; kp0 += 16) {
        for (int idx = tid; idx < 64 * 16; idx += 256) {
            int kp = idx & 15, m = idx >> 4;
            uint2 v = Apk[(size_t)m * kKP + kp0 + kp];
            Ah[m][kp] = v.x; Al[m][kp] = v.y;
        }
        for (int idx = tid; idx < 64 * 16; idx += 256) {
            int kp = idx & 15, j = idx >> 4;
            uint2 v = g_wopk[(size_t)(c0 + j) * kKP + kp0 + kp];
            Bh[j][kp] = v.x; Bl[j][kp] = v.y;
        }
        __syncthreads();
#pragma unroll
        for (int kt = 0; kt < 2; kt++) {
            uint32_t ah[4], al[4];
            ah[0] = Ah[wm + grp][kt * 8 + tg];         al[0] = Al[wm + grp][kt * 8 + tg];
            ah[1] = Ah[wm + grp + 8][kt * 8 + tg];     al[1] = Al[wm + grp + 8][kt * 8 + tg];
            ah[2] = Ah[wm + grp][kt * 8 + tg + 4];     al[2] = Al[wm + grp][kt * 8 + tg + 4];
            ah[3] = Ah[wm + grp + 8][kt * 8 + tg + 4]; al[3] = Al[wm + grp + 8][kt * 8 + tg + 4];
#pragma unroll
            for (int nt = 0; nt < 4; nt++) {
                const int jj = wn + nt * 8 + grp;
                uint32_t bh[2], bl[2];
                bh[0] = Bh[jj][kt * 8 + tg];     bl[0] = Bl[jj][kt * 8 + tg];
                bh[1] = Bh[jj][kt * 8 + tg + 4]; bl[1] = Bl[jj][kt * 8 + tg + 4];
                mma16(acc[nt], ah, bh);
                mma16(acc[nt], ah, bl);
                mma16(acc[nt], al, bh);
            }
        }
        __syncthreads();
    }

#pragma unroll
    for (int nt = 0; nt < 4; nt++) {
#pragma unroll
        for (int cc = 0; cc < 4; cc++) {
            int b   = wm + grp + ((cc & 2) ? 8 : 0);
            int col = c0 + wn + nt * 8 + 2 * tg + (cc & 1);
            float v = acc[nt][cc] + bo[col];
            out[((size_t)b * kT + t) * kDout + col] = fmaxf(v, 0.0f);
        }
    }
}

// ---------------- h_final copy ----------------------------------------------

__global__ void final_copy_kernel(float* __restrict__ out) {
    int i = blockIdx.x * blockDim.x + threadIdx.x;
    if (i < kB * kDh)
        out[(size_t)kB * kT * kDout + i] = g_hs[(size_t)kT * kB * kDh + i];
}

// ---------------- launch ------------------------------------------------------
// d_in: inputs, Wz, bz, Wr, br, Ws, bs, Wo, bo ; d_out: [outputs | h_final] fp32

extern "C" void kernel_launch(void* const* d_in, const int* in_sizes, int n_in,
                              void* d_out, int out_size) {
    (void)in_sizes; (void)n_in; (void)out_size;
    const float* inp = (const float*)d_in[0];
    const float* Wz  = (const float*)d_in[1];
    const float* bz  = (const float*)d_in[2];
    const float* Wr  = (const float*)d_in[3];
    const float* br  = (const float*)d_in[4];
    const float* Ws  = (const float*)d_in[5];
    const float* bs  = (const float*)d_in[6];
    const float* Wo  = (const float*)d_in[7];
    const float* bo  = (const float*)d_in[8];
    float* out = (float*)d_out;

    cudaFuncSetAttribute(recur_kernel, cudaFuncAttributeMaxDynamicSharedMemorySize,
                         (int)kSmemBytes);

    zero_h0_kernel<<<(kB * kDh + 255) / 256, 256>>>();
    prep_w_kernel<<<(3 * kKP * kDh + 255) / 256, 256>>>(Wz, Wr, Ws);
    prep_wx_kernel<<<(3 * kDh * kKPx + 255) / 256, 256>>>(Wz, Wr, Ws);
    prep_wo_kernel<<<(kDout * kKP + 255) / 256, 256>>>(Wo);
    prep_in_kernel<<<(kB * kT * kKPx + 255) / 256, 256>>>(inp);
    proj_x_kernel<<<dim3(kB * kT / 64, 3 * kDh / 64), 256>>>(bz, br, bs);
    recur_kernel<<<kNC, 512, kSmemBytes>>>();
    out_proj_kernel<<<dim3(kT, kDout / 64), 256>>>(bo, out);
    final_copy_kernel<<<(kB * kDh + 255) / 256, 256>>>(out);
}